// round 10
// baseline (speedup 1.0000x reference)
#include <cuda_runtime.h>
#include <cuda_fp16.h>
#include <math.h>
#include <stdint.h>

#define D_MODEL 1024
#define D_INNER 2048
#define D_STATE 16
#define D_CONV  4
#define DT_RANK 64
#define BATCH   2
#define SEQLEN  1024
#define BL      (BATCH * SEQLEN)          // 2048 rows
#define XPROJ   (DT_RANK + 2 * D_STATE)   // 96
#define KSPLIT  8
#define PCHUNK  4                          // parallel scan chunks
#define CHLEN   (SEQLEN / PCHUNK)          // 256 steps per chunk

// ---------------- scratch (static device globals; no allocs allowed) -------
__device__ __align__(16) __half g_xzh [(size_t)BL * 2 * D_INNER];   // 16 MB
__device__ __align__(16) float  g_xc  [(size_t)BL * D_INNER];       // 16 MB
__device__ __align__(16) __half g_xch [(size_t)BL * D_INNER];
__device__ __align__(16) float  g_xdbl[(size_t)BL * XPROJ];
__device__ __align__(16) float  g_part[(size_t)KSPLIT * BL * XPROJ];
__device__ __align__(16) __half g_dth [(size_t)BL * DT_RANK];
__device__ __align__(16) float  g_delta[(size_t)BL * D_INNER];      // 16 MB
__device__ __align__(16) __half g_yh  [(size_t)BL * D_INNER];
__device__ __align__(16) __half g_hh  [(size_t)BL * D_MODEL];
__device__ __align__(16) __half g_w1h [(size_t)2 * D_INNER * D_MODEL];
__device__ __align__(16) __half g_w3h [(size_t)XPROJ * D_INNER];
__device__ __align__(16) __half g_w4h [(size_t)D_INNER * DT_RANK];
__device__ __align__(16) __half g_w6h [(size_t)D_MODEL * D_INNER];
// scan chunk summaries: [b][chunk][d][n]
__device__ __align__(16) float  g_sloc[(size_t)BATCH * PCHUNK * D_INNER * D_STATE];
__device__ __align__(16) float  g_ddec[(size_t)BATCH * PCHUNK * D_INNER * D_STATE];

// ---------------- tiny PTX helpers -----------------------------------------
__device__ __forceinline__ uint32_t smem_u32(const void* p) {
    uint32_t a;
    asm("{ .reg .u64 t; cvta.to.shared.u64 t, %1; cvt.u32.u64 %0, t; }"
        : "=r"(a) : "l"(p));
    return a;
}
__device__ __forceinline__ uint32_t sw128(uint32_t off) {
    return off ^ ((off >> 3) & 0x70);
}
__device__ __forceinline__ void cpa16(uint32_t dst, const void* src, bool valid) {
    int sz = valid ? 16 : 0;
    asm volatile("cp.async.cg.shared.global [%0], [%1], 16, %2;"
                 :: "r"(dst), "l"(src), "r"(sz));
}
__device__ __forceinline__ void cpa16ca(uint32_t dst, const void* src) {
    asm volatile("cp.async.ca.shared.global [%0], [%1], 16;"
                 :: "r"(dst), "l"(src));
}
__device__ __forceinline__ void ldsm4(uint32_t* r, uint32_t addr) {
    asm volatile("ldmatrix.sync.aligned.m8n8.x4.shared.b16 {%0,%1,%2,%3}, [%4];"
                 : "=r"(r[0]), "=r"(r[1]), "=r"(r[2]), "=r"(r[3]) : "r"(addr));
}
__device__ __forceinline__ void mma_f16(float* d, const uint32_t* a,
                                        uint32_t b0, uint32_t b1) {
    asm volatile(
        "mma.sync.aligned.m16n8k16.row.col.f32.f16.f16.f32 "
        "{%0,%1,%2,%3}, {%4,%5,%6,%7}, {%8,%9}, {%0,%1,%2,%3};"
        : "+f"(d[0]), "+f"(d[1]), "+f"(d[2]), "+f"(d[3])
        : "r"(a[0]), "r"(a[1]), "r"(a[2]), "r"(a[3]), "r"(b0), "r"(b1));
}

// ---------------- fp32 -> fp16 conversions ----------------------------------
__global__ void cvt_kernel(const float* __restrict__ x,
                           __half* __restrict__ h, int n4)
{
    int i = blockIdx.x * blockDim.x + threadIdx.x;
    if (i < n4) {
        float4 v = ((const float4*)x)[i];
        __half2 a = __floats2half2_rn(v.x, v.y);
        __half2 b = __floats2half2_rn(v.z, v.w);
        ((uint2*)h)[i] = make_uint2(*(uint32_t*)&a, *(uint32_t*)&b);
    }
}
__global__ void cvt3_kernel(const float* __restrict__ w6,
                            const float* __restrict__ w3,
                            const float* __restrict__ w4)
{
    const int N6 = D_MODEL * D_INNER / 4;
    const int N3 = XPROJ * D_INNER / 4;
    const int N4 = D_INNER * DT_RANK / 4;
    int j = blockIdx.x * blockDim.x + threadIdx.x;
    const float* src; __half* dst;
    if (j < N6)              { src = w6; dst = g_w6h; }
    else if ((j -= N6) < N3) { src = w3; dst = g_w3h; }
    else if ((j -= N3) < N4) { src = w4; dst = g_w4h; }
    else return;
    float4 v = ((const float4*)src)[j];
    __half2 a = __floats2half2_rn(v.x, v.y);
    __half2 b = __floats2half2_rn(v.z, v.w);
    ((uint2*)dst)[j] = make_uint2(*(uint32_t*)&a, *(uint32_t*)&b);
}

// ---------------- HMMA fp16 GEMM -------------------------------------------
// C[M,N] = A[M,K] * B[N,K]^T, fp16 in, fp32 accum.
// 128x128 CTA; 8 warps 4(M)x2(N); warp tile 32x64.
// K-chunk = KH*64 (KH=1 or 2); chunk stored as KH 16KB SW128 sub-tiles.
// 3-stage cp.async, one __syncthreads per chunk.
// EPI: 0=fp32 store, 1=bias+softplus fp32, 2=fp16 store (C is __half*).
#define NSTAGE   3
#define THALF    16384

template <int EPI, int KH>
__global__ __launch_bounds__(256)
void gemm_f16(const __half* __restrict__ A, int lda,
              const __half* __restrict__ B, int ldb,
              void* __restrict__ Cv, int ldc,
              int M, int N, int Kslice,
              const float* __restrict__ bias)
{
    extern __shared__ __align__(16) char dyns[];

    const int TILE_SZ  = KH * THALF;           // bytes per A (or B) tile
    const int STAGE_SZ = 2 * TILE_SZ;

    const int tid  = threadIdx.x;
    const int wid  = tid >> 5;
    const int lane = tid & 31;
    const int row0 = blockIdx.y * 128;
    const int col0 = blockIdx.x * 128;
    const int kBeg = blockIdx.z * Kslice;
    const int nB = min(128, N - col0);
    const int chunks = Kslice / (KH * 64);

    float*  Cf = (float*)Cv  + (size_t)blockIdx.z * (size_t)M * (size_t)ldc;
    __half* Ch = (__half*)Cv;

    const int warp_m = wid & 3;
    const int warp_n = wid >> 2;

    uint32_t sbase = (smem_u32(dyns) + 1023u) & ~1023u;

    float acc[2][8][4];
#pragma unroll
    for (int i = 0; i < 2; i++)
#pragma unroll
        for (int j = 0; j < 8; j++)
#pragma unroll
            for (int k = 0; k < 4; k++) acc[i][j][k] = 0.f;

    auto load_chunk = [&](int c) {
        uint32_t st = sbase + (uint32_t)(c % NSTAGE) * STAGE_SZ;
        int seg = tid & 7;
#pragma unroll
        for (int hh = 0; hh < KH; hh++) {
            int kcol = kBeg + c * KH * 64 + hh * 64;
#pragma unroll
            for (int j = 0; j < 4; j++) {
                int row = (tid >> 3) + j * 32;
                uint32_t so = sw128((uint32_t)(row * 128 + seg * 16)) + hh * THALF;
                const __half* pa = A + (size_t)(row0 + row) * lda + kcol + seg * 8;
                cpa16(st + so, pa, true);
                bool bv = row < nB;
                int  br = bv ? row : 0;
                const __half* pb = B + (size_t)(col0 + br) * ldb + kcol + seg * 8;
                cpa16(st + TILE_SZ + so, pb, bv);
            }
        }
        asm volatile("cp.async.commit_group;" ::: "memory");
    };

#pragma unroll
    for (int p = 0; p < NSTAGE - 1; p++)
        if (p < chunks) load_chunk(p);

    const int lrow  = lane & 15;
    const int lhalf = lane >> 4;

    uint32_t swa[2], swb[4];
#pragma unroll
    for (int mf = 0; mf < 2; mf++)
        swa[mf] = sw128((uint32_t)((warp_m * 32 + mf * 16 + lrow) * 128));
#pragma unroll
    for (int nf = 0; nf < 4; nf++)
        swb[nf] = sw128((uint32_t)((warp_n * 64 + nf * 16 + lrow) * 128)) + TILE_SZ;

    for (int c = 0; c < chunks; c++) {
        int pend = chunks - 1 - c;
        if (pend > NSTAGE - 2) pend = NSTAGE - 2;
        if (pend == 1) asm volatile("cp.async.wait_group 1;" ::: "memory");
        else           asm volatile("cp.async.wait_group 0;" ::: "memory");
        __syncthreads();      // single barrier per chunk

        if (c + NSTAGE - 1 < chunks) load_chunk(c + NSTAGE - 1);

        uint32_t st = sbase + (uint32_t)(c % NSTAGE) * STAGE_SZ;

#pragma unroll
        for (int ks = 0; ks < KH * 4; ks++) {
            const uint32_t hofs = (uint32_t)(ks >> 2) * THALF;
            const uint32_t kb = (uint32_t)((ks & 3) * 32 + lhalf * 16);
            uint32_t af[2][4], bf[4][4];
            ldsm4(af[0], (st + hofs + swa[0]) ^ kb);
            ldsm4(af[1], (st + hofs + swa[1]) ^ kb);
            ldsm4(bf[0], (st + hofs + swb[0]) ^ kb);
            ldsm4(bf[1], (st + hofs + swb[1]) ^ kb);
            ldsm4(bf[2], (st + hofs + swb[2]) ^ kb);
            ldsm4(bf[3], (st + hofs + swb[3]) ^ kb);
#pragma unroll
            for (int mf = 0; mf < 2; mf++) {
#pragma unroll
                for (int nf = 0; nf < 4; nf++) {
                    mma_f16(acc[mf][2 * nf],     af[mf], bf[nf][0], bf[nf][2]);
                    mma_f16(acc[mf][2 * nf + 1], af[mf], bf[nf][1], bf[nf][3]);
                }
            }
        }
    }
    __syncthreads();

#pragma unroll
    for (int mf = 0; mf < 2; mf++) {
        int r = row0 + warp_m * 32 + mf * 16 + (lane >> 2);
#pragma unroll
        for (int j = 0; j < 8; j++) {
            int ccol = col0 + warp_n * 64 + j * 8 + (lane & 3) * 2;
            if (ccol < N) {
                float v0 = acc[mf][j][0], v1 = acc[mf][j][1];
                float v2 = acc[mf][j][2], v3 = acc[mf][j][3];
                if (EPI == 1) {
                    v0 += bias[ccol];     v1 += bias[ccol + 1];
                    v2 += bias[ccol];     v3 += bias[ccol + 1];
                    v0 = (v0 > 20.f) ? v0 : log1pf(__expf(v0));
                    v1 = (v1 > 20.f) ? v1 : log1pf(__expf(v1));
                    v2 = (v2 > 20.f) ? v2 : log1pf(__expf(v2));
                    v3 = (v3 > 20.f) ? v3 : log1pf(__expf(v3));
                }
                if (EPI == 2) {
                    __half2 h0 = __floats2half2_rn(v0, v1);
                    __half2 h1 = __floats2half2_rn(v2, v3);
                    *(__half2*)&Ch[(size_t)r * ldc + ccol]       = h0;
                    *(__half2*)&Ch[(size_t)(r + 8) * ldc + ccol] = h1;
                } else {
                    *(float2*)&Cf[(size_t)r * ldc + ccol]       = make_float2(v0, v1);
                    *(float2*)&Cf[(size_t)(r + 8) * ldc + ccol] = make_float2(v2, v3);
                }
            }
        }
    }
}

// ---------------- reduce split-K partials + dt_lr fp16 ----------------------
__global__ void reduce_part_kernel()
{
    int i = blockIdx.x * blockDim.x + threadIdx.x;
    if (i < BL * XPROJ) {
        float s = 0.f;
#pragma unroll
        for (int p = 0; p < KSPLIT; p++)
            s += g_part[(size_t)p * BL * XPROJ + i];
        g_xdbl[i] = s;
        int col = i % XPROJ;
        if (col < DT_RANK) {
            int row = i / XPROJ;
            g_dth[(size_t)row * DT_RANK + col] = __float2half_rn(s);
        }
    }
}

// ---------------- depthwise causal conv + bias + SiLU (4 ch/thread) --------
__global__ void conv_silu_kernel(const float* __restrict__ w,
                                 const float* __restrict__ bias)
{
    int idx = blockIdx.x * blockDim.x + threadIdx.x;   // one per 4 channels
    if (idx >= BL * D_INNER / 4) return;
    int d4 = idx % (D_INNER / 4);
    int bl = idx / (D_INNER / 4);
    int l  = bl % SEQLEN;
    int d  = d4 * 4;

    float4 acc = *(const float4*)&bias[d];
    float4 wv[4];
#pragma unroll
    for (int c = 0; c < 4; c++) wv[c] = *(const float4*)&w[(d + c) * D_CONV];

#pragma unroll
    for (int k = 0; k < D_CONV; k++) {
        int lk = l - (D_CONV - 1) + k;
        if (lk >= 0) {
            uint2 xr = *(const uint2*)&g_xzh[(size_t)(bl - (D_CONV - 1 - k)) * (2 * D_INNER) + d];
            float2 x01 = __half22float2(*(__half2*)&xr.x);
            float2 x23 = __half22float2(*(__half2*)&xr.y);
            acc.x = fmaf(((const float*)&wv[0])[k], x01.x, acc.x);
            acc.y = fmaf(((const float*)&wv[1])[k], x01.y, acc.y);
            acc.z = fmaf(((const float*)&wv[2])[k], x23.x, acc.z);
            acc.w = fmaf(((const float*)&wv[3])[k], x23.y, acc.w);
        }
    }
    float4 v;
    v.x = acc.x / (1.f + __expf(-acc.x));
    v.y = acc.y / (1.f + __expf(-acc.y));
    v.z = acc.z / (1.f + __expf(-acc.z));
    v.w = acc.w / (1.f + __expf(-acc.w));
    *(float4*)&g_xc[(size_t)bl * D_INNER + d] = v;
    __half2 h0 = __floats2half2_rn(v.x, v.y);
    __half2 h1 = __floats2half2_rn(v.z, v.w);
    *(uint2*)&g_xch[(size_t)bl * D_INNER + d] =
        make_uint2(*(uint32_t*)&h0, *(uint32_t*)&h1);
}

// ---------------- chunked selective scan ------------------------------------
// PHASE 0: per chunk local scan from 0; emit s_loc + decay.
// PHASE 1: inline prefix over chunk summaries -> true start state; scan,
//          emit gated y (fp16).
#define TL 64
template <int PHASE>
__global__ __launch_bounds__(512)
void scan_phase(const float* __restrict__ A_log,
                const float* __restrict__ D_skip)
{
    __shared__ float sD[2][TL][32];
    __shared__ float sU[2][TL][32];
    __shared__ float sB[2][TL][16];
    __shared__ float sC[2][TL][16];
    __shared__ float sY[TL][32];

    const int b    = blockIdx.y;
    const int ck   = blockIdx.z;
    const int d0   = blockIdx.x * 32;
    const int tid  = threadIdx.x;
    const int dc   = tid >> 4;
    const int n    = tid & 15;
    const int d    = d0 + dc;
    const int lbase = ck * CHLEN;

    const float An = -__expf(A_log[d * D_STATE + n]);

    float s = 0.f;
    if (PHASE == 1) {
        for (int c = 0; c < ck; c++) {
            size_t idx = ((size_t)(b * PCHUNK + c) * D_INNER + d) * D_STATE + n;
            s = s * g_ddec[idx] + g_sloc[idx];
        }
    }
    float sumdl = 0.f;
    const float Dskip = D_skip[d0 + (tid & 31)];

    auto stage = [&](int j) {
        int buf = j & 1;
        int l0 = lbase + j * TL;
        {
            int t = tid >> 3, seg = tid & 7;
            size_t row = (size_t)(b * SEQLEN + l0 + t);
            cpa16ca(smem_u32(&sD[buf][t][seg * 4]),
                    &g_delta[row * D_INNER + d0 + seg * 4]);
            cpa16ca(smem_u32(&sU[buf][t][seg * 4]),
                    &g_xc[row * D_INNER + d0 + seg * 4]);
        }
        if (tid < 256) {
            int t = tid >> 2, seg = tid & 3;
            size_t row = (size_t)(b * SEQLEN + l0 + t);
            cpa16ca(smem_u32(&sB[buf][t][seg * 4]),
                    &g_xdbl[row * XPROJ + DT_RANK + seg * 4]);
        } else if (PHASE == 1) {
            int t2 = tid - 256;
            int t = t2 >> 2, seg = t2 & 3;
            size_t row = (size_t)(b * SEQLEN + l0 + t);
            cpa16ca(smem_u32(&sC[buf][t][seg * 4]),
                    &g_xdbl[row * XPROJ + DT_RANK + D_STATE + seg * 4]);
        }
        asm volatile("cp.async.commit_group;" ::: "memory");
    };

    const int NJ = CHLEN / TL;   // 4 sub-chunks
    stage(0);

    for (int j = 0; j < NJ; j++) {
        if (j + 1 < NJ) {
            stage(j + 1);
            asm volatile("cp.async.wait_group 1;" ::: "memory");
        } else {
            asm volatile("cp.async.wait_group 0;" ::: "memory");
        }
        __syncthreads();

        const int buf = j & 1;
#pragma unroll 4
        for (int t = 0; t < TL; t++) {
            float dl = sD[buf][t][dc];
            float u  = sU[buf][t][dc];
            float dA = __expf(dl * An);
            s = fmaf(s, dA, (dl * u) * sB[buf][t][n]);
            if (PHASE == 0) {
                sumdl += dl;
            } else {
                float v = s * sC[buf][t][n];
                v += __shfl_xor_sync(0xffffffffu, v, 8);
                v += __shfl_xor_sync(0xffffffffu, v, 4);
                v += __shfl_xor_sync(0xffffffffu, v, 2);
                v += __shfl_xor_sync(0xffffffffu, v, 1);
                if (n == 0) sY[t][dc] = v;
            }
        }

        if (PHASE == 1) {
            __syncthreads();
            int l0 = lbase + j * TL;
            for (int i = tid; i < TL * 32; i += 512) {
                int t = i >> 5, ch = i & 31;
                size_t row = (size_t)(b * SEQLEN + l0 + t);
                float u  = sU[buf][t][ch];
                float yv = sY[t][ch] + u * Dskip;
                float z  = __half2float(g_xzh[row * (2 * D_INNER) + D_INNER + d0 + ch]);
                yv *= z / (1.f + __expf(-z));
                g_yh[row * D_INNER + d0 + ch] = __float2half_rn(yv);
            }
        }
        __syncthreads();
    }

    if (PHASE == 0) {
        size_t sumIdx = ((size_t)(b * PCHUNK + ck) * D_INNER + d) * D_STATE + n;
        g_sloc[sumIdx] = s;
        g_ddec[sumIdx] = __expf(An * sumdl);
    }
}

// ---------------- launcher --------------------------------------------------
extern "C" void kernel_launch(void* const* d_in, const int* in_sizes, int n_in,
                              void* d_out, int out_size)
{
    const float* hidden     = (const float*)d_in[0];
    const float* in_proj_w  = (const float*)d_in[1];
    const float* conv_w     = (const float*)d_in[2];
    const float* conv_b     = (const float*)d_in[3];
    const float* x_proj_w   = (const float*)d_in[4];
    const float* dt_proj_w  = (const float*)d_in[5];
    const float* dt_proj_b  = (const float*)d_in[6];
    const float* A_log      = (const float*)d_in[7];
    const float* D_skip     = (const float*)d_in[8];
    const float* out_proj_w = (const float*)d_in[9];
    float* out = (float*)d_out;

    const int SM64  = 2 * 2 * THALF * NSTAGE / 2 + 1024;   // KH=1: 96KB+1K
    const int SM128 = 2 * 2 * THALF * NSTAGE + 1024;       // KH=2: 192KB+1K

    cudaFuncSetAttribute(gemm_f16<0, 1>,
                         cudaFuncAttributeMaxDynamicSharedMemorySize, SM64);
    cudaFuncSetAttribute(gemm_f16<1, 1>,
                         cudaFuncAttributeMaxDynamicSharedMemorySize, SM64);
    cudaFuncSetAttribute(gemm_f16<0, 2>,
                         cudaFuncAttributeMaxDynamicSharedMemorySize, SM128);
    cudaFuncSetAttribute(gemm_f16<2, 2>,
                         cudaFuncAttributeMaxDynamicSharedMemorySize, SM128);

    float *xdbl, *part, *delta;
    __half *xzh, *xch, *dth, *yh, *hh, *w1h, *w3h, *w4h, *w6h;
    cudaGetSymbolAddress((void**)&xzh,   g_xzh);
    cudaGetSymbolAddress((void**)&xdbl,  g_xdbl);
    cudaGetSymbolAddress((void**)&part,  g_part);
    cudaGetSymbolAddress((void**)&delta, g_delta);
    cudaGetSymbolAddress((void**)&xch,   g_xch);
    cudaGetSymbolAddress((void**)&dth,   g_dth);
    cudaGetSymbolAddress((void**)&yh,    g_yh);
    cudaGetSymbolAddress((void**)&hh,    g_hh);
    cudaGetSymbolAddress((void**)&w1h,   g_w1h);
    cudaGetSymbolAddress((void**)&w3h,   g_w3h);
    cudaGetSymbolAddress((void**)&w4h,   g_w4h);
    cudaGetSymbolAddress((void**)&w6h,   g_w6h);

    // launches 0-2: conversions (keeps gemm1 at ncu capture index 3)
    cvt_kernel<<<(2 * D_INNER * D_MODEL / 4 + 255) / 256, 256>>>(
        in_proj_w, w1h, 2 * D_INNER * D_MODEL / 4);
    cvt_kernel<<<(BL * D_MODEL / 4 + 255) / 256, 256>>>(
        hidden, hh, BL * D_MODEL / 4);
    {
        int total = (D_MODEL * D_INNER + XPROJ * D_INNER + D_INNER * DT_RANK) / 4;
        cvt3_kernel<<<(total + 255) / 256, 256>>>(out_proj_w, x_proj_w, dt_proj_w);
    }

    // 1) xz = hidden @ in_proj_w^T   (2048 x 4096 x 1024) -> fp16, KC=128
    gemm_f16<2, 2><<<dim3(4096 / 128, BL / 128, 1), 256, SM128>>>(
        hh, D_MODEL, w1h, D_MODEL, xzh, 2 * D_INNER,
        BL, 2 * D_INNER, D_MODEL, nullptr);

    // 2) depthwise conv + SiLU -> xc (fp32) + xch (fp16)
    conv_silu_kernel<<<(BL * D_INNER / 4 + 255) / 256, 256>>>(conv_w, conv_b);

    // 3) x_dbl = xc @ x_proj_w^T    (2048 x 96 x 2048), split-K=8 + reduce
    gemm_f16<0, 1><<<dim3(1, BL / 128, KSPLIT), 256, SM64>>>(
        xch, D_INNER, w3h, D_INNER, part, XPROJ,
        BL, XPROJ, D_INNER / KSPLIT, nullptr);
    reduce_part_kernel<<<(BL * XPROJ + 255) / 256, 256>>>();

    // 4) delta = softplus(dt_lr @ dt_proj_w^T + dt_b)  (2048 x 2048 x 64)
    gemm_f16<1, 1><<<dim3(D_INNER / 128, BL / 128, 1), 256, SM64>>>(
        dth, DT_RANK, w4h, DT_RANK, delta, D_INNER,
        BL, D_INNER, DT_RANK, dt_proj_b);

    // 5) chunked selective scan: local pass, then final pass (prefix inlined)
    scan_phase<0><<<dim3(D_INNER / 32, BATCH, PCHUNK), 512>>>(A_log, D_skip);
    scan_phase<1><<<dim3(D_INNER / 32, BATCH, PCHUNK), 512>>>(A_log, D_skip);

    // 6) out = y @ out_proj_w^T     (2048 x 1024 x 2048), KC=128
    gemm_f16<0, 2><<<dim3(D_MODEL / 128, BL / 128, 1), 256, SM128>>>(
        yh, D_INNER, w6h, D_INNER, out, D_MODEL,
        BL, D_MODEL, D_INNER, nullptr);
}

// round 12
// speedup vs baseline: 1.0133x; 1.0133x over previous
#include <cuda_runtime.h>
#include <cuda_fp16.h>
#include <math.h>
#include <stdint.h>

#define D_MODEL 1024
#define D_INNER 2048
#define D_STATE 16
#define D_CONV  4
#define DT_RANK 64
#define BATCH   2
#define SEQLEN  1024
#define BL      (BATCH * SEQLEN)          // 2048 rows
#define XPROJ   (DT_RANK + 2 * D_STATE)   // 96
#define KSPLIT  8
#define PCHUNK  4                          // parallel scan chunks
#define CHLEN   (SEQLEN / PCHUNK)          // 256 steps per chunk

// ---------------- scratch (static device globals; no allocs allowed) -------
__device__ __align__(16) __half g_xzh [(size_t)BL * 2 * D_INNER];   // 16 MB
__device__ __align__(16) float  g_xc  [(size_t)BL * D_INNER];       // 16 MB
__device__ __align__(16) __half g_xch [(size_t)BL * D_INNER];
__device__ __align__(16) float  g_xdbl[(size_t)BL * XPROJ];
__device__ __align__(16) float  g_part[(size_t)KSPLIT * BL * XPROJ];
__device__ __align__(16) __half g_dth [(size_t)BL * DT_RANK];
__device__ __align__(16) float  g_delta[(size_t)BL * D_INNER];      // 16 MB
__device__ __align__(16) __half g_yh  [(size_t)BL * D_INNER];
__device__ __align__(16) __half g_hh  [(size_t)BL * D_MODEL];
__device__ __align__(16) __half g_w1h [(size_t)2 * D_INNER * D_MODEL];
__device__ __align__(16) __half g_w3h [(size_t)XPROJ * D_INNER];
__device__ __align__(16) __half g_w4h [(size_t)D_INNER * DT_RANK];
__device__ __align__(16) __half g_w6h [(size_t)D_MODEL * D_INNER];
// scan chunk summaries: [b][chunk][d][n]
__device__ __align__(16) float  g_sloc[(size_t)BATCH * PCHUNK * D_INNER * D_STATE];
__device__ __align__(16) float  g_ddec[(size_t)BATCH * PCHUNK * D_INNER * D_STATE];

// ---------------- tiny PTX helpers -----------------------------------------
__device__ __forceinline__ uint32_t smem_u32(const void* p) {
    uint32_t a;
    asm("{ .reg .u64 t; cvta.to.shared.u64 t, %1; cvt.u32.u64 %0, t; }"
        : "=r"(a) : "l"(p));
    return a;
}
__device__ __forceinline__ uint32_t sw128(uint32_t off) {
    return off ^ ((off >> 3) & 0x70);
}
__device__ __forceinline__ void cpa16(uint32_t dst, const void* src, bool valid) {
    int sz = valid ? 16 : 0;
    asm volatile("cp.async.cg.shared.global [%0], [%1], 16, %2;"
                 :: "r"(dst), "l"(src), "r"(sz));
}
__device__ __forceinline__ void cpa16ca(uint32_t dst, const void* src) {
    asm volatile("cp.async.ca.shared.global [%0], [%1], 16;"
                 :: "r"(dst), "l"(src));
}
__device__ __forceinline__ void ldsm4(uint32_t* r, uint32_t addr) {
    asm volatile("ldmatrix.sync.aligned.m8n8.x4.shared.b16 {%0,%1,%2,%3}, [%4];"
                 : "=r"(r[0]), "=r"(r[1]), "=r"(r[2]), "=r"(r[3]) : "r"(addr));
}
__device__ __forceinline__ void mma_f16(float* d, const uint32_t* a,
                                        uint32_t b0, uint32_t b1) {
    asm volatile(
        "mma.sync.aligned.m16n8k16.row.col.f32.f16.f16.f32 "
        "{%0,%1,%2,%3}, {%4,%5,%6,%7}, {%8,%9}, {%0,%1,%2,%3};"
        : "+f"(d[0]), "+f"(d[1]), "+f"(d[2]), "+f"(d[3])
        : "r"(a[0]), "r"(a[1]), "r"(a[2]), "r"(a[3]), "r"(b0), "r"(b1));
}

// ---------------- fp32 -> fp16 conversions ----------------------------------
__global__ void cvt_kernel(const float* __restrict__ x,
                           __half* __restrict__ h, int n4)
{
    int i = blockIdx.x * blockDim.x + threadIdx.x;
    if (i < n4) {
        float4 v = ((const float4*)x)[i];
        __half2 a = __floats2half2_rn(v.x, v.y);
        __half2 b = __floats2half2_rn(v.z, v.w);
        ((uint2*)h)[i] = make_uint2(*(uint32_t*)&a, *(uint32_t*)&b);
    }
}
__global__ void cvt3_kernel(const float* __restrict__ w6,
                            const float* __restrict__ w3,
                            const float* __restrict__ w4)
{
    const int N6 = D_MODEL * D_INNER / 4;
    const int N3 = XPROJ * D_INNER / 4;
    const int N4 = D_INNER * DT_RANK / 4;
    int j = blockIdx.x * blockDim.x + threadIdx.x;
    const float* src; __half* dst;
    if (j < N6)              { src = w6; dst = g_w6h; }
    else if ((j -= N6) < N3) { src = w3; dst = g_w3h; }
    else if ((j -= N3) < N4) { src = w4; dst = g_w4h; }
    else return;
    float4 v = ((const float4*)src)[j];
    __half2 a = __floats2half2_rn(v.x, v.y);
    __half2 b = __floats2half2_rn(v.z, v.w);
    ((uint2*)dst)[j] = make_uint2(*(uint32_t*)&a, *(uint32_t*)&b);
}

// ---------------- HMMA fp16 GEMM, 256 thr, 128x128 tile --------------------
// C[M,N] = A[M,K] * B[N,K]^T, fp16 in, fp32 accum.
// 8 warps 4(M)x2(N); warp tile 32x64; KC=64; 3-stage cp.async; one barrier
// per chunk.  EPI: 0=fp32 store, 1=bias+softplus fp32, 2=fp16 store.
#define KC 64
#define TILE_B   (128 * 128)
#define STAGE_B  (2 * TILE_B)
#define NSTAGE   3
#define GEMM_SMEM (NSTAGE * STAGE_B + 1024)

template <int EPI>
__global__ __launch_bounds__(256, 2)
void gemm_f16(const __half* __restrict__ A, int lda,
              const __half* __restrict__ B, int ldb,
              void* __restrict__ Cv, int ldc,
              int M, int N, int Kslice,
              const float* __restrict__ bias)
{
    extern __shared__ __align__(16) char dyns[];

    const int tid  = threadIdx.x;
    const int wid  = tid >> 5;
    const int lane = tid & 31;
    const int row0 = blockIdx.y * 128;
    const int col0 = blockIdx.x * 128;
    const int kBeg = blockIdx.z * Kslice;
    const int nB = min(128, N - col0);
    const int chunks = Kslice / KC;

    float*  Cf = (float*)Cv  + (size_t)blockIdx.z * (size_t)M * (size_t)ldc;
    __half* Ch = (__half*)Cv;

    const int warp_m = wid & 3;
    const int warp_n = wid >> 2;

    uint32_t sbase = (smem_u32(dyns) + 1023u) & ~1023u;

    float acc[2][8][4];
#pragma unroll
    for (int i = 0; i < 2; i++)
#pragma unroll
        for (int j = 0; j < 8; j++)
#pragma unroll
            for (int k = 0; k < 4; k++) acc[i][j][k] = 0.f;

    auto load_chunk = [&](int c) {
        uint32_t st = sbase + (uint32_t)(c % NSTAGE) * STAGE_B;
        int kcol = kBeg + c * KC;
        int seg = tid & 7;
#pragma unroll
        for (int j = 0; j < 4; j++) {
            int row = (tid >> 3) + j * 32;
            uint32_t so = sw128((uint32_t)(row * 128 + seg * 16));
            const __half* pa = A + (size_t)(row0 + row) * lda + kcol + seg * 8;
            cpa16(st + so, pa, true);
            bool bv = row < nB;
            int  br = bv ? row : 0;
            const __half* pb = B + (size_t)(col0 + br) * ldb + kcol + seg * 8;
            cpa16(st + TILE_B + so, pb, bv);
        }
        asm volatile("cp.async.commit_group;" ::: "memory");
    };

#pragma unroll
    for (int p = 0; p < NSTAGE - 1; p++)
        if (p < chunks) load_chunk(p);

    const int lrow  = lane & 15;
    const int lhalf = lane >> 4;

    uint32_t swa[2], swb[4];
#pragma unroll
    for (int mf = 0; mf < 2; mf++)
        swa[mf] = sw128((uint32_t)((warp_m * 32 + mf * 16 + lrow) * 128));
#pragma unroll
    for (int nf = 0; nf < 4; nf++)
        swb[nf] = sw128((uint32_t)((warp_n * 64 + nf * 16 + lrow) * 128)) + TILE_B;

    for (int c = 0; c < chunks; c++) {
        int pend = chunks - 1 - c;
        if (pend > NSTAGE - 2) pend = NSTAGE - 2;
        if (pend == 1) asm volatile("cp.async.wait_group 1;" ::: "memory");
        else           asm volatile("cp.async.wait_group 0;" ::: "memory");
        __syncthreads();

        if (c + NSTAGE - 1 < chunks) load_chunk(c + NSTAGE - 1);

        uint32_t st = sbase + (uint32_t)(c % NSTAGE) * STAGE_B;

#pragma unroll
        for (int ks = 0; ks < KC / 16; ks++) {
            const uint32_t kb = (uint32_t)(ks * 32 + lhalf * 16);
            uint32_t af[2][4], bf[4][4];
            ldsm4(af[0], (st + swa[0]) ^ kb);
            ldsm4(af[1], (st + swa[1]) ^ kb);
            ldsm4(bf[0], (st + swb[0]) ^ kb);
            ldsm4(bf[1], (st + swb[1]) ^ kb);
            ldsm4(bf[2], (st + swb[2]) ^ kb);
            ldsm4(bf[3], (st + swb[3]) ^ kb);
#pragma unroll
            for (int mf = 0; mf < 2; mf++) {
#pragma unroll
                for (int nf = 0; nf < 4; nf++) {
                    mma_f16(acc[mf][2 * nf],     af[mf], bf[nf][0], bf[nf][2]);
                    mma_f16(acc[mf][2 * nf + 1], af[mf], bf[nf][1], bf[nf][3]);
                }
            }
        }
    }
    __syncthreads();

#pragma unroll
    for (int mf = 0; mf < 2; mf++) {
        int r = row0 + warp_m * 32 + mf * 16 + (lane >> 2);
#pragma unroll
        for (int j = 0; j < 8; j++) {
            int ccol = col0 + warp_n * 64 + j * 8 + (lane & 3) * 2;
            if (ccol < N) {
                float v0 = acc[mf][j][0], v1 = acc[mf][j][1];
                float v2 = acc[mf][j][2], v3 = acc[mf][j][3];
                if (EPI == 1) {
                    v0 += bias[ccol];     v1 += bias[ccol + 1];
                    v2 += bias[ccol];     v3 += bias[ccol + 1];
                    v0 = (v0 > 20.f) ? v0 : log1pf(__expf(v0));
                    v1 = (v1 > 20.f) ? v1 : log1pf(__expf(v1));
                    v2 = (v2 > 20.f) ? v2 : log1pf(__expf(v2));
                    v3 = (v3 > 20.f) ? v3 : log1pf(__expf(v3));
                }
                if (EPI == 2) {
                    __half2 h0 = __floats2half2_rn(v0, v1);
                    __half2 h1 = __floats2half2_rn(v2, v3);
                    *(__half2*)&Ch[(size_t)r * ldc + ccol]       = h0;
                    *(__half2*)&Ch[(size_t)(r + 8) * ldc + ccol] = h1;
                } else {
                    *(float2*)&Cf[(size_t)r * ldc + ccol]       = make_float2(v0, v1);
                    *(float2*)&Cf[(size_t)(r + 8) * ldc + ccol] = make_float2(v2, v3);
                }
            }
        }
    }
}

// ---------------- HMMA fp16 GEMM, 512 thr, 128(M)x256(N) tile --------------
// 16 warps 4(M)x4(N); warp tile 32x64; KC=64; 3-stage (48KB/stage);
// fp16 output (for GEMM1).  4 warps/SMSP for latency hiding.
#define WTILE_A  (128 * 128)              // 16 KB
#define WTILE_B  (256 * 128)              // 32 KB
#define WSTAGE   (WTILE_A + WTILE_B)      // 48 KB
#define WSMEM    (NSTAGE * WSTAGE + 1024)

__global__ __launch_bounds__(512, 1)
void gemm_f16_w512(const __half* __restrict__ A, int lda,
                   const __half* __restrict__ B, int ldb,
                   __half* __restrict__ C, int ldc,
                   int M, int N, int K)
{
    extern __shared__ __align__(16) char dyns[];

    const int tid  = threadIdx.x;
    const int wid  = tid >> 5;
    const int lane = tid & 31;
    const int row0 = blockIdx.y * 128;
    const int col0 = blockIdx.x * 256;
    const int chunks = K / KC;

    const int warp_m = wid & 3;           // 0..3 -> 32 rows
    const int warp_n = wid >> 2;          // 0..3 -> 64 cols

    uint32_t sbase = (smem_u32(dyns) + 1023u) & ~1023u;

    float acc[2][8][4];
#pragma unroll
    for (int i = 0; i < 2; i++)
#pragma unroll
        for (int j = 0; j < 8; j++)
#pragma unroll
            for (int k = 0; k < 4; k++) acc[i][j][k] = 0.f;

    auto load_chunk = [&](int c) {
        uint32_t st = sbase + (uint32_t)(c % NSTAGE) * WSTAGE;
        int kcol = c * KC;
        int seg = tid & 7;
        int rb  = tid >> 3;               // 0..63
        // A: 128 rows
#pragma unroll
        for (int j = 0; j < 2; j++) {
            int row = rb + j * 64;
            uint32_t so = sw128((uint32_t)(row * 128 + seg * 16));
            cpa16(st + so, A + (size_t)(row0 + row) * lda + kcol + seg * 8, true);
        }
        // B: 256 rows
#pragma unroll
        for (int j = 0; j < 4; j++) {
            int row = rb + j * 64;
            uint32_t so = sw128((uint32_t)(row * 128 + seg * 16));
            cpa16(st + WTILE_A + so,
                  B + (size_t)(col0 + row) * ldb + kcol + seg * 8, true);
        }
        asm volatile("cp.async.commit_group;" ::: "memory");
    };

#pragma unroll
    for (int p = 0; p < NSTAGE - 1; p++)
        if (p < chunks) load_chunk(p);

    const int lrow  = lane & 15;
    const int lhalf = lane >> 4;

    uint32_t swa[2], swb[4];
#pragma unroll
    for (int mf = 0; mf < 2; mf++)
        swa[mf] = sw128((uint32_t)((warp_m * 32 + mf * 16 + lrow) * 128));
#pragma unroll
    for (int nf = 0; nf < 4; nf++)
        swb[nf] = sw128((uint32_t)((warp_n * 64 + nf * 16 + lrow) * 128)) + WTILE_A;

    for (int c = 0; c < chunks; c++) {
        int pend = chunks - 1 - c;
        if (pend > NSTAGE - 2) pend = NSTAGE - 2;
        if (pend == 1) asm volatile("cp.async.wait_group 1;" ::: "memory");
        else           asm volatile("cp.async.wait_group 0;" ::: "memory");
        __syncthreads();

        if (c + NSTAGE - 1 < chunks) load_chunk(c + NSTAGE - 1);

        uint32_t st = sbase + (uint32_t)(c % NSTAGE) * WSTAGE;

#pragma unroll
        for (int ks = 0; ks < KC / 16; ks++) {
            const uint32_t kb = (uint32_t)(ks * 32 + lhalf * 16);
            uint32_t af[2][4], bf[4][4];
            ldsm4(af[0], (st + swa[0]) ^ kb);
            ldsm4(af[1], (st + swa[1]) ^ kb);
            ldsm4(bf[0], (st + swb[0]) ^ kb);
            ldsm4(bf[1], (st + swb[1]) ^ kb);
            ldsm4(bf[2], (st + swb[2]) ^ kb);
            ldsm4(bf[3], (st + swb[3]) ^ kb);
#pragma unroll
            for (int mf = 0; mf < 2; mf++) {
#pragma unroll
                for (int nf = 0; nf < 4; nf++) {
                    mma_f16(acc[mf][2 * nf],     af[mf], bf[nf][0], bf[nf][2]);
                    mma_f16(acc[mf][2 * nf + 1], af[mf], bf[nf][1], bf[nf][3]);
                }
            }
        }
    }
    __syncthreads();

#pragma unroll
    for (int mf = 0; mf < 2; mf++) {
        int r = row0 + warp_m * 32 + mf * 16 + (lane >> 2);
#pragma unroll
        for (int j = 0; j < 8; j++) {
            int ccol = col0 + warp_n * 64 + j * 8 + (lane & 3) * 2;
            __half2 h0 = __floats2half2_rn(acc[mf][j][0], acc[mf][j][1]);
            __half2 h1 = __floats2half2_rn(acc[mf][j][2], acc[mf][j][3]);
            *(__half2*)&C[(size_t)r * ldc + ccol]       = h0;
            *(__half2*)&C[(size_t)(r + 8) * ldc + ccol] = h1;
        }
    }
}

// ---------------- reduce split-K partials + dt_lr fp16 ----------------------
__global__ void reduce_part_kernel()
{
    int i = blockIdx.x * blockDim.x + threadIdx.x;
    if (i < BL * XPROJ) {
        float s = 0.f;
#pragma unroll
        for (int p = 0; p < KSPLIT; p++)
            s += g_part[(size_t)p * BL * XPROJ + i];
        g_xdbl[i] = s;
        int col = i % XPROJ;
        if (col < DT_RANK) {
            int row = i / XPROJ;
            g_dth[(size_t)row * DT_RANK + col] = __float2half_rn(s);
        }
    }
}

// ---------------- depthwise causal conv + bias + SiLU (4 ch/thread) --------
__global__ void conv_silu_kernel(const float* __restrict__ w,
                                 const float* __restrict__ bias)
{
    int idx = blockIdx.x * blockDim.x + threadIdx.x;   // one per 4 channels
    if (idx >= BL * D_INNER / 4) return;
    int d4 = idx % (D_INNER / 4);
    int bl = idx / (D_INNER / 4);
    int l  = bl % SEQLEN;
    int d  = d4 * 4;

    float4 acc = *(const float4*)&bias[d];
    float4 wv[4];
#pragma unroll
    for (int c = 0; c < 4; c++) wv[c] = *(const float4*)&w[(d + c) * D_CONV];

#pragma unroll
    for (int k = 0; k < D_CONV; k++) {
        int lk = l - (D_CONV - 1) + k;
        if (lk >= 0) {
            uint2 xr = *(const uint2*)&g_xzh[(size_t)(bl - (D_CONV - 1 - k)) * (2 * D_INNER) + d];
            float2 x01 = __half22float2(*(__half2*)&xr.x);
            float2 x23 = __half22float2(*(__half2*)&xr.y);
            acc.x = fmaf(((const float*)&wv[0])[k], x01.x, acc.x);
            acc.y = fmaf(((const float*)&wv[1])[k], x01.y, acc.y);
            acc.z = fmaf(((const float*)&wv[2])[k], x23.x, acc.z);
            acc.w = fmaf(((const float*)&wv[3])[k], x23.y, acc.w);
        }
    }
    float4 v;
    v.x = acc.x / (1.f + __expf(-acc.x));
    v.y = acc.y / (1.f + __expf(-acc.y));
    v.z = acc.z / (1.f + __expf(-acc.z));
    v.w = acc.w / (1.f + __expf(-acc.w));
    *(float4*)&g_xc[(size_t)bl * D_INNER + d] = v;
    __half2 h0 = __floats2half2_rn(v.x, v.y);
    __half2 h1 = __floats2half2_rn(v.z, v.w);
    *(uint2*)&g_xch[(size_t)bl * D_INNER + d] =
        make_uint2(*(uint32_t*)&h0, *(uint32_t*)&h1);
}

// ---------------- chunked selective scan ------------------------------------
#define TL 64
template <int PHASE>
__global__ __launch_bounds__(512)
void scan_phase(const float* __restrict__ A_log,
                const float* __restrict__ D_skip)
{
    __shared__ float sD[2][TL][32];
    __shared__ float sU[2][TL][32];
    __shared__ float sB[2][TL][16];
    __shared__ float sC[2][TL][16];
    __shared__ float sY[TL][32];

    const int b    = blockIdx.y;
    const int ck   = blockIdx.z;
    const int d0   = blockIdx.x * 32;
    const int tid  = threadIdx.x;
    const int dc   = tid >> 4;
    const int n    = tid & 15;
    const int d    = d0 + dc;
    const int lbase = ck * CHLEN;

    const float An = -__expf(A_log[d * D_STATE + n]);

    float s = 0.f;
    if (PHASE == 1) {
        for (int c = 0; c < ck; c++) {
            size_t idx = ((size_t)(b * PCHUNK + c) * D_INNER + d) * D_STATE + n;
            s = s * g_ddec[idx] + g_sloc[idx];
        }
    }
    float sumdl = 0.f;
    const float Dskip = D_skip[d0 + (tid & 31)];

    auto stage = [&](int j) {
        int buf = j & 1;
        int l0 = lbase + j * TL;
        {
            int t = tid >> 3, seg = tid & 7;
            size_t row = (size_t)(b * SEQLEN + l0 + t);
            cpa16ca(smem_u32(&sD[buf][t][seg * 4]),
                    &g_delta[row * D_INNER + d0 + seg * 4]);
            cpa16ca(smem_u32(&sU[buf][t][seg * 4]),
                    &g_xc[row * D_INNER + d0 + seg * 4]);
        }
        if (tid < 256) {
            int t = tid >> 2, seg = tid & 3;
            size_t row = (size_t)(b * SEQLEN + l0 + t);
            cpa16ca(smem_u32(&sB[buf][t][seg * 4]),
                    &g_xdbl[row * XPROJ + DT_RANK + seg * 4]);
        } else if (PHASE == 1) {
            int t2 = tid - 256;
            int t = t2 >> 2, seg = t2 & 3;
            size_t row = (size_t)(b * SEQLEN + l0 + t);
            cpa16ca(smem_u32(&sC[buf][t][seg * 4]),
                    &g_xdbl[row * XPROJ + DT_RANK + D_STATE + seg * 4]);
        }
        asm volatile("cp.async.commit_group;" ::: "memory");
    };

    const int NJ = CHLEN / TL;   // 4 sub-chunks
    stage(0);

    for (int j = 0; j < NJ; j++) {
        if (j + 1 < NJ) {
            stage(j + 1);
            asm volatile("cp.async.wait_group 1;" ::: "memory");
        } else {
            asm volatile("cp.async.wait_group 0;" ::: "memory");
        }
        __syncthreads();

        const int buf = j & 1;
#pragma unroll 4
        for (int t = 0; t < TL; t++) {
            float dl = sD[buf][t][dc];
            float u  = sU[buf][t][dc];
            float dA = __expf(dl * An);
            s = fmaf(s, dA, (dl * u) * sB[buf][t][n]);
            if (PHASE == 0) {
                sumdl += dl;
            } else {
                float v = s * sC[buf][t][n];
                v += __shfl_xor_sync(0xffffffffu, v, 8);
                v += __shfl_xor_sync(0xffffffffu, v, 4);
                v += __shfl_xor_sync(0xffffffffu, v, 2);
                v += __shfl_xor_sync(0xffffffffu, v, 1);
                if (n == 0) sY[t][dc] = v;
            }
        }

        if (PHASE == 1) {
            __syncthreads();
            int l0 = lbase + j * TL;
            for (int i = tid; i < TL * 32; i += 512) {
                int t = i >> 5, ch = i & 31;
                size_t row = (size_t)(b * SEQLEN + l0 + t);
                float u  = sU[buf][t][ch];
                float yv = sY[t][ch] + u * Dskip;
                float z  = __half2float(g_xzh[row * (2 * D_INNER) + D_INNER + d0 + ch]);
                yv *= z / (1.f + __expf(-z));
                g_yh[row * D_INNER + d0 + ch] = __float2half_rn(yv);
            }
        }
        __syncthreads();
    }

    if (PHASE == 0) {
        size_t sumIdx = ((size_t)(b * PCHUNK + ck) * D_INNER + d) * D_STATE + n;
        g_sloc[sumIdx] = s;
        g_ddec[sumIdx] = __expf(An * sumdl);
    }
}

// ---------------- launcher --------------------------------------------------
extern "C" void kernel_launch(void* const* d_in, const int* in_sizes, int n_in,
                              void* d_out, int out_size)
{
    const float* hidden     = (const float*)d_in[0];
    const float* in_proj_w  = (const float*)d_in[1];
    const float* conv_w     = (const float*)d_in[2];
    const float* conv_b     = (const float*)d_in[3];
    const float* x_proj_w   = (const float*)d_in[4];
    const float* dt_proj_w  = (const float*)d_in[5];
    const float* dt_proj_b  = (const float*)d_in[6];
    const float* A_log      = (const float*)d_in[7];
    const float* D_skip     = (const float*)d_in[8];
    const float* out_proj_w = (const float*)d_in[9];
    float* out = (float*)d_out;

    cudaFuncSetAttribute(gemm_f16<0>,
                         cudaFuncAttributeMaxDynamicSharedMemorySize, GEMM_SMEM);
    cudaFuncSetAttribute(gemm_f16<1>,
                         cudaFuncAttributeMaxDynamicSharedMemorySize, GEMM_SMEM);
    cudaFuncSetAttribute(gemm_f16_w512,
                         cudaFuncAttributeMaxDynamicSharedMemorySize, WSMEM);

    float *xdbl, *part, *delta;
    __half *xzh, *xch, *dth, *yh, *hh, *w1h, *w3h, *w4h, *w6h;
    cudaGetSymbolAddress((void**)&xzh,   g_xzh);
    cudaGetSymbolAddress((void**)&xdbl,  g_xdbl);
    cudaGetSymbolAddress((void**)&part,  g_part);
    cudaGetSymbolAddress((void**)&delta, g_delta);
    cudaGetSymbolAddress((void**)&xch,   g_xch);
    cudaGetSymbolAddress((void**)&dth,   g_dth);
    cudaGetSymbolAddress((void**)&yh,    g_yh);
    cudaGetSymbolAddress((void**)&hh,    g_hh);
    cudaGetSymbolAddress((void**)&w1h,   g_w1h);
    cudaGetSymbolAddress((void**)&w3h,   g_w3h);
    cudaGetSymbolAddress((void**)&w4h,   g_w4h);
    cudaGetSymbolAddress((void**)&w6h,   g_w6h);

    // launches 0-2: conversions (keeps gemm1 at ncu capture index 3)
    cvt_kernel<<<(2 * D_INNER * D_MODEL / 4 + 255) / 256, 256>>>(
        in_proj_w, w1h, 2 * D_INNER * D_MODEL / 4);
    cvt_kernel<<<(BL * D_MODEL / 4 + 255) / 256, 256>>>(
        hidden, hh, BL * D_MODEL / 4);
    {
        int total = (D_MODEL * D_INNER + XPROJ * D_INNER + D_INNER * DT_RANK) / 4;
        cvt3_kernel<<<(total + 255) / 256, 256>>>(out_proj_w, x_proj_w, dt_proj_w);
    }

    // 1) xz = hidden @ in_proj_w^T   (2048 x 4096 x 1024) -> fp16, 512-thr
    gemm_f16_w512<<<dim3(4096 / 256, BL / 128, 1), 512, WSMEM>>>(
        hh, D_MODEL, w1h, D_MODEL, xzh, 2 * D_INNER,
        BL, 2 * D_INNER, D_MODEL);

    // 2) depthwise conv + SiLU -> xc (fp32) + xch (fp16)
    conv_silu_kernel<<<(BL * D_INNER / 4 + 255) / 256, 256>>>(conv_w, conv_b);

    // 3) x_dbl = xc @ x_proj_w^T    (2048 x 96 x 2048), split-K=8 + reduce
    gemm_f16<0><<<dim3(1, BL / 128, KSPLIT), 256, GEMM_SMEM>>>(
        xch, D_INNER, w3h, D_INNER, part, XPROJ,
        BL, XPROJ, D_INNER / KSPLIT, nullptr);
    reduce_part_kernel<<<(BL * XPROJ + 255) / 256, 256>>>();

    // 4) delta = softplus(dt_lr @ dt_proj_w^T + dt_b)  (2048 x 2048 x 64)
    gemm_f16<1><<<dim3(D_INNER / 128, BL / 128, 1), 256, GEMM_SMEM>>>(
        dth, DT_RANK, w4h, DT_RANK, delta, D_INNER,
        BL, D_INNER, DT_RANK, dt_proj_b);

    // 5) chunked selective scan: local pass, then final pass (prefix inlined)
    scan_phase<0><<<dim3(D_INNER / 32, BATCH, PCHUNK), 512>>>(A_log, D_skip);
    scan_phase<1><<<dim3(D_INNER / 32, BATCH, PCHUNK), 512>>>(A_log, D_skip);

    // 6) out = y @ out_proj_w^T     (2048 x 1024 x 2048)
    gemm_f16<0><<<dim3(D_MODEL / 128, BL / 128, 1), 256, GEMM_SMEM>>>(
        yh, D_INNER, w6h, D_INNER, out, D_MODEL,
        BL, D_MODEL, D_INNER, nullptr);
}

// round 15
// speedup vs baseline: 1.0218x; 1.0084x over previous
#include <cuda_runtime.h>
#include <cuda_fp16.h>
#include <math.h>
#include <stdint.h>

#define D_MODEL 1024
#define D_INNER 2048
#define D_STATE 16
#define D_CONV  4
#define DT_RANK 64
#define BATCH   2
#define SEQLEN  1024
#define BL      (BATCH * SEQLEN)          // 2048 rows
#define XPROJ   (DT_RANK + 2 * D_STATE)   // 96
#define KSPLIT  8
#define PCHUNK  4                          // parallel scan chunks
#define CHLEN   (SEQLEN / PCHUNK)          // 256 steps per chunk

// ---------------- scratch (static device globals; no allocs allowed) -------
__device__ __align__(16) __half g_xzh [(size_t)BL * 2 * D_INNER];   // 16 MB
__device__ __align__(16) float  g_xc  [(size_t)BL * D_INNER];       // 16 MB
__device__ __align__(16) __half g_xch [(size_t)BL * D_INNER];
__device__ __align__(16) float  g_xdbl[(size_t)BL * XPROJ];
__device__ __align__(16) float  g_part[(size_t)KSPLIT * BL * XPROJ];
__device__ __align__(16) __half g_dth [(size_t)BL * DT_RANK];
__device__ __align__(16) float  g_delta[(size_t)BL * D_INNER];      // 16 MB
__device__ __align__(16) __half g_yh  [(size_t)BL * D_INNER];
__device__ __align__(16) __half g_hh  [(size_t)BL * D_MODEL];
__device__ __align__(16) __half g_w1h [(size_t)2 * D_INNER * D_MODEL];
__device__ __align__(16) __half g_w3h [(size_t)XPROJ * D_INNER];
__device__ __align__(16) __half g_w4h [(size_t)D_INNER * DT_RANK];
__device__ __align__(16) __half g_w6h [(size_t)D_MODEL * D_INNER];
// scan chunk summaries: [b][chunk][d][n]
__device__ __align__(16) float  g_sloc[(size_t)BATCH * PCHUNK * D_INNER * D_STATE];
__device__ __align__(16) float  g_ddec[(size_t)BATCH * PCHUNK * D_INNER * D_STATE];

// ---------------- tiny PTX helpers -----------------------------------------
__device__ __forceinline__ uint32_t smem_u32(const void* p) {
    uint32_t a;
    asm("{ .reg .u64 t; cvta.to.shared.u64 t, %1; cvt.u32.u64 %0, t; }"
        : "=r"(a) : "l"(p));
    return a;
}
__device__ __forceinline__ uint32_t sw128(uint32_t off) {
    return off ^ ((off >> 3) & 0x70);
}
__device__ __forceinline__ void cpa16(uint32_t dst, const void* src, bool valid) {
    int sz = valid ? 16 : 0;
    asm volatile("cp.async.cg.shared.global [%0], [%1], 16, %2;"
                 :: "r"(dst), "l"(src), "r"(sz));
}
__device__ __forceinline__ void cpa16ca(uint32_t dst, const void* src) {
    asm volatile("cp.async.ca.shared.global [%0], [%1], 16;"
                 :: "r"(dst), "l"(src));
}
__device__ __forceinline__ void ldsm4(uint32_t* r, uint32_t addr) {
    asm volatile("ldmatrix.sync.aligned.m8n8.x4.shared.b16 {%0,%1,%2,%3}, [%4];"
                 : "=r"(r[0]), "=r"(r[1]), "=r"(r[2]), "=r"(r[3]) : "r"(addr));
}
__device__ __forceinline__ void mma_f16(float* d, const uint32_t* a,
                                        uint32_t b0, uint32_t b1) {
    asm volatile(
        "mma.sync.aligned.m16n8k16.row.col.f32.f16.f16.f32 "
        "{%0,%1,%2,%3}, {%4,%5,%6,%7}, {%8,%9}, {%0,%1,%2,%3};"
        : "+f"(d[0]), "+f"(d[1]), "+f"(d[2]), "+f"(d[3])
        : "r"(a[0]), "r"(a[1]), "r"(a[2]), "r"(a[3]), "r"(b0), "r"(b1));
}

// ---------------- fp32 -> fp16 conversions ----------------------------------
__global__ void cvt_kernel(const float* __restrict__ x,
                           __half* __restrict__ h, int n4)
{
    int i = blockIdx.x * blockDim.x + threadIdx.x;
    if (i < n4) {
        float4 v = ((const float4*)x)[i];
        __half2 a = __floats2half2_rn(v.x, v.y);
        __half2 b = __floats2half2_rn(v.z, v.w);
        ((uint2*)h)[i] = make_uint2(*(uint32_t*)&a, *(uint32_t*)&b);
    }
}
__global__ void cvt3_kernel(const float* __restrict__ w6,
                            const float* __restrict__ w3,
                            const float* __restrict__ w4)
{
    const int N6 = D_MODEL * D_INNER / 4;
    const int N3 = XPROJ * D_INNER / 4;
    const int N4 = D_INNER * DT_RANK / 4;
    int j = blockIdx.x * blockDim.x + threadIdx.x;
    const float* src; __half* dst;
    if (j < N6)              { src = w6; dst = g_w6h; }
    else if ((j -= N6) < N3) { src = w3; dst = g_w3h; }
    else if ((j -= N3) < N4) { src = w4; dst = g_w4h; }
    else return;
    float4 v = ((const float4*)src)[j];
    __half2 a = __floats2half2_rn(v.x, v.y);
    __half2 b = __floats2half2_rn(v.z, v.w);
    ((uint2*)dst)[j] = make_uint2(*(uint32_t*)&a, *(uint32_t*)&b);
}

// ---------------- HMMA fp16 GEMM, 256 thr, 128x128 tile --------------------
// C[M,N] = A[M,K] * B[N,K]^T, fp16 in, fp32 accum.
// 8 warps 4(M)x2(N); warp tile 32x64; KC=64; 3-stage cp.async; one barrier
// per chunk.  EPI: 0=fp32 store, 1=bias+softplus fp32.
#define KC 64
#define TILE_B   (128 * 128)
#define STAGE_B  (2 * TILE_B)
#define NSTAGE   3
#define GEMM_SMEM (NSTAGE * STAGE_B + 1024)

template <int EPI>
__global__ __launch_bounds__(256, 2)
void gemm_f16(const __half* __restrict__ A, int lda,
              const __half* __restrict__ B, int ldb,
              float* __restrict__ C, int ldc,
              int M, int N, int Kslice,
              const float* __restrict__ bias)
{
    extern __shared__ __align__(16) char dyns[];

    const int tid  = threadIdx.x;
    const int wid  = tid >> 5;
    const int lane = tid & 31;
    const int row0 = blockIdx.y * 128;
    const int col0 = blockIdx.x * 128;
    const int kBeg = blockIdx.z * Kslice;
    const int nB = min(128, N - col0);
    const int chunks = Kslice / KC;

    float* Cf = C + (size_t)blockIdx.z * (size_t)M * (size_t)ldc;

    const int warp_m = wid & 3;
    const int warp_n = wid >> 2;

    uint32_t sbase = (smem_u32(dyns) + 1023u) & ~1023u;

    float acc[2][8][4];
#pragma unroll
    for (int i = 0; i < 2; i++)
#pragma unroll
        for (int j = 0; j < 8; j++)
#pragma unroll
            for (int k = 0; k < 4; k++) acc[i][j][k] = 0.f;

    auto load_chunk = [&](int c) {
        uint32_t st = sbase + (uint32_t)(c % NSTAGE) * STAGE_B;
        int kcol = kBeg + c * KC;
        int seg = tid & 7;
#pragma unroll
        for (int j = 0; j < 4; j++) {
            int row = (tid >> 3) + j * 32;
            uint32_t so = sw128((uint32_t)(row * 128 + seg * 16));
            const __half* pa = A + (size_t)(row0 + row) * lda + kcol + seg * 8;
            cpa16(st + so, pa, true);
            bool bv = row < nB;
            int  br = bv ? row : 0;
            const __half* pb = B + (size_t)(col0 + br) * ldb + kcol + seg * 8;
            cpa16(st + TILE_B + so, pb, bv);
        }
        asm volatile("cp.async.commit_group;" ::: "memory");
    };

#pragma unroll
    for (int p = 0; p < NSTAGE - 1; p++)
        if (p < chunks) load_chunk(p);

    const int lrow  = lane & 15;
    const int lhalf = lane >> 4;

    uint32_t swa[2], swb[4];
#pragma unroll
    for (int mf = 0; mf < 2; mf++)
        swa[mf] = sw128((uint32_t)((warp_m * 32 + mf * 16 + lrow) * 128));
#pragma unroll
    for (int nf = 0; nf < 4; nf++)
        swb[nf] = sw128((uint32_t)((warp_n * 64 + nf * 16 + lrow) * 128)) + TILE_B;

    for (int c = 0; c < chunks; c++) {
        int pend = chunks - 1 - c;
        if (pend > NSTAGE - 2) pend = NSTAGE - 2;
        if (pend == 1) asm volatile("cp.async.wait_group 1;" ::: "memory");
        else           asm volatile("cp.async.wait_group 0;" ::: "memory");
        __syncthreads();

        if (c + NSTAGE - 1 < chunks) load_chunk(c + NSTAGE - 1);

        uint32_t st = sbase + (uint32_t)(c % NSTAGE) * STAGE_B;

#pragma unroll
        for (int ks = 0; ks < KC / 16; ks++) {
            const uint32_t kb = (uint32_t)(ks * 32 + lhalf * 16);
            uint32_t af[2][4], bf[4][4];
            ldsm4(af[0], (st + swa[0]) ^ kb);
            ldsm4(af[1], (st + swa[1]) ^ kb);
            ldsm4(bf[0], (st + swb[0]) ^ kb);
            ldsm4(bf[1], (st + swb[1]) ^ kb);
            ldsm4(bf[2], (st + swb[2]) ^ kb);
            ldsm4(bf[3], (st + swb[3]) ^ kb);
#pragma unroll
            for (int mf = 0; mf < 2; mf++) {
#pragma unroll
                for (int nf = 0; nf < 4; nf++) {
                    mma_f16(acc[mf][2 * nf],     af[mf], bf[nf][0], bf[nf][2]);
                    mma_f16(acc[mf][2 * nf + 1], af[mf], bf[nf][1], bf[nf][3]);
                }
            }
        }
    }
    __syncthreads();

#pragma unroll
    for (int mf = 0; mf < 2; mf++) {
        int r = row0 + warp_m * 32 + mf * 16 + (lane >> 2);
#pragma unroll
        for (int j = 0; j < 8; j++) {
            int ccol = col0 + warp_n * 64 + j * 8 + (lane & 3) * 2;
            if (ccol < N) {
                float v0 = acc[mf][j][0], v1 = acc[mf][j][1];
                float v2 = acc[mf][j][2], v3 = acc[mf][j][3];
                if (EPI == 1) {
                    v0 += bias[ccol];     v1 += bias[ccol + 1];
                    v2 += bias[ccol];     v3 += bias[ccol + 1];
                    v0 = (v0 > 20.f) ? v0 : log1pf(__expf(v0));
                    v1 = (v1 > 20.f) ? v1 : log1pf(__expf(v1));
                    v2 = (v2 > 20.f) ? v2 : log1pf(__expf(v2));
                    v3 = (v3 > 20.f) ? v3 : log1pf(__expf(v3));
                }
                *(float2*)&Cf[(size_t)r * ldc + ccol]       = make_float2(v0, v1);
                *(float2*)&Cf[(size_t)(r + 8) * ldc + ccol] = make_float2(v2, v3);
            }
        }
    }
}

// ---------------- HMMA fp16 GEMM, 256 thr, 128(M)x256(N), 64x64 warp tile --
// 8 warps 2(M)x4(N); warp tile 64x64 -> 8 ldsm per 32 mma (LDSM-traffic
// optimized).  KC=64; 3-stage (48KB/stage); fp16 output (GEMM1).
#define WTILE_A  (128 * 128)              // 16 KB
#define WTILE_B  (256 * 128)              // 32 KB
#define WSTAGE   (WTILE_A + WTILE_B)      // 48 KB
#define WSMEM    (NSTAGE * WSTAGE + 1024)

__global__ __launch_bounds__(256, 1)
void gemm_w64(const __half* __restrict__ A, int lda,
              const __half* __restrict__ B, int ldb,
              __half* __restrict__ C, int ldc,
              int M, int N, int K)
{
    extern __shared__ __align__(16) char dyns[];

    const int tid  = threadIdx.x;
    const int wid  = tid >> 5;
    const int lane = tid & 31;
    const int row0 = blockIdx.y * 128;
    const int col0 = blockIdx.x * 256;
    const int chunks = K / KC;

    const int warp_m = wid & 1;           // 0..1 -> 64 rows
    const int warp_n = wid >> 1;          // 0..3 -> 64 cols

    uint32_t sbase = (smem_u32(dyns) + 1023u) & ~1023u;

    float acc[4][8][4];
#pragma unroll
    for (int i = 0; i < 4; i++)
#pragma unroll
        for (int j = 0; j < 8; j++)
#pragma unroll
            for (int k = 0; k < 4; k++) acc[i][j][k] = 0.f;

    auto load_chunk = [&](int c) {
        uint32_t st = sbase + (uint32_t)(c % NSTAGE) * WSTAGE;
        int kcol = c * KC;
        int seg = tid & 7;
        int rb  = tid >> 3;               // 0..31
        // A: 128 rows x 128B
#pragma unroll
        for (int j = 0; j < 4; j++) {
            int row = rb + j * 32;
            uint32_t so = sw128((uint32_t)(row * 128 + seg * 16));
            cpa16(st + so, A + (size_t)(row0 + row) * lda + kcol + seg * 8, true);
        }
        // B: 256 rows x 128B
#pragma unroll
        for (int j = 0; j < 8; j++) {
            int row = rb + j * 32;
            uint32_t so = sw128((uint32_t)(row * 128 + seg * 16));
            cpa16(st + WTILE_A + so,
                  B + (size_t)(col0 + row) * ldb + kcol + seg * 8, true);
        }
        asm volatile("cp.async.commit_group;" ::: "memory");
    };

#pragma unroll
    for (int p = 0; p < NSTAGE - 1; p++)
        if (p < chunks) load_chunk(p);

    const int lrow  = lane & 15;
    const int lhalf = lane >> 4;

    uint32_t swa[4], swb[4];
#pragma unroll
    for (int mf = 0; mf < 4; mf++)
        swa[mf] = sw128((uint32_t)((warp_m * 64 + mf * 16 + lrow) * 128));
#pragma unroll
    for (int nf = 0; nf < 4; nf++)
        swb[nf] = sw128((uint32_t)((warp_n * 64 + nf * 16 + lrow) * 128)) + WTILE_A;

    for (int c = 0; c < chunks; c++) {
        int pend = chunks - 1 - c;
        if (pend > NSTAGE - 2) pend = NSTAGE - 2;
        if (pend == 1) asm volatile("cp.async.wait_group 1;" ::: "memory");
        else           asm volatile("cp.async.wait_group 0;" ::: "memory");
        __syncthreads();

        if (c + NSTAGE - 1 < chunks) load_chunk(c + NSTAGE - 1);

        uint32_t st = sbase + (uint32_t)(c % NSTAGE) * WSTAGE;

#pragma unroll
        for (int ks = 0; ks < KC / 16; ks++) {
            const uint32_t kb = (uint32_t)(ks * 32 + lhalf * 16);
            uint32_t af[4][4], bf[4][4];
#pragma unroll
            for (int mf = 0; mf < 4; mf++) ldsm4(af[mf], (st + swa[mf]) ^ kb);
#pragma unroll
            for (int nf = 0; nf < 4; nf++) ldsm4(bf[nf], (st + swb[nf]) ^ kb);
#pragma unroll
            for (int mf = 0; mf < 4; mf++) {
#pragma unroll
                for (int nf = 0; nf < 4; nf++) {
                    mma_f16(acc[mf][2 * nf],     af[mf], bf[nf][0], bf[nf][2]);
                    mma_f16(acc[mf][2 * nf + 1], af[mf], bf[nf][1], bf[nf][3]);
                }
            }
        }
    }
    __syncthreads();

#pragma unroll
    for (int mf = 0; mf < 4; mf++) {
        int r = row0 + warp_m * 64 + mf * 16 + (lane >> 2);
#pragma unroll
        for (int j = 0; j < 8; j++) {
            int ccol = col0 + warp_n * 64 + j * 8 + (lane & 3) * 2;
            __half2 h0 = __floats2half2_rn(acc[mf][j][0], acc[mf][j][1]);
            __half2 h1 = __floats2half2_rn(acc[mf][j][2], acc[mf][j][3]);
            *(__half2*)&C[(size_t)r * ldc + ccol]       = h0;
            *(__half2*)&C[(size_t)(r + 8) * ldc + ccol] = h1;
        }
    }
}

// ---------------- reduce split-K partials + dt_lr fp16 ----------------------
__global__ void reduce_part_kernel()
{
    int i = blockIdx.x * blockDim.x + threadIdx.x;
    if (i < BL * XPROJ) {
        float s = 0.f;
#pragma unroll
        for (int p = 0; p < KSPLIT; p++)
            s += g_part[(size_t)p * BL * XPROJ + i];
        g_xdbl[i] = s;
        int col = i % XPROJ;
        if (col < DT_RANK) {
            int row = i / XPROJ;
            g_dth[(size_t)row * DT_RANK + col] = __float2half_rn(s);
        }
    }
}

// ---------------- depthwise causal conv + bias + SiLU -----------------------
__global__ void conv_silu_kernel(const float* __restrict__ w,
                                 const float* __restrict__ bias)
{
    int idx = blockIdx.x * blockDim.x + threadIdx.x;
    if (idx >= BL * D_INNER) return;
    int d  = idx % D_INNER;
    int bl = idx / D_INNER;
    int l  = bl % SEQLEN;

    float acc = bias[d];
#pragma unroll
    for (int k = 0; k < D_CONV; k++) {
        int lk = l - (D_CONV - 1) + k;
        if (lk >= 0)
            acc += w[d * D_CONV + k] *
                   __half2float(g_xzh[(size_t)(bl - (D_CONV - 1 - k)) * (2 * D_INNER) + d]);
    }
    float sg = 1.f / (1.f + __expf(-acc));
    float v = acc * sg;
    g_xc[idx]  = v;
    g_xch[idx] = __float2half_rn(v);
}

// ---------------- chunked selective scan ------------------------------------
#define TL 64
template <int PHASE>
__global__ __launch_bounds__(512)
void scan_phase(const float* __restrict__ A_log,
                const float* __restrict__ D_skip)
{
    __shared__ float sD[2][TL][32];
    __shared__ float sU[2][TL][32];
    __shared__ float sB[2][TL][16];
    __shared__ float sC[2][TL][16];
    __shared__ float sY[TL][32];

    const int b    = blockIdx.y;
    const int ck   = blockIdx.z;
    const int d0   = blockIdx.x * 32;
    const int tid  = threadIdx.x;
    const int dc   = tid >> 4;
    const int n    = tid & 15;
    const int d    = d0 + dc;
    const int lbase = ck * CHLEN;

    const float An = -__expf(A_log[d * D_STATE + n]);

    float s = 0.f;
    if (PHASE == 1) {
        for (int c = 0; c < ck; c++) {
            size_t idx = ((size_t)(b * PCHUNK + c) * D_INNER + d) * D_STATE + n;
            s = s * g_ddec[idx] + g_sloc[idx];
        }
    }
    float sumdl = 0.f;
    const float Dskip = D_skip[d0 + (tid & 31)];

    auto stage = [&](int j) {
        int buf = j & 1;
        int l0 = lbase + j * TL;
        {
            int t = tid >> 3, seg = tid & 7;
            size_t row = (size_t)(b * SEQLEN + l0 + t);
            cpa16ca(smem_u32(&sD[buf][t][seg * 4]),
                    &g_delta[row * D_INNER + d0 + seg * 4]);
            cpa16ca(smem_u32(&sU[buf][t][seg * 4]),
                    &g_xc[row * D_INNER + d0 + seg * 4]);
        }
        if (tid < 256) {
            int t = tid >> 2, seg = tid & 3;
            size_t row = (size_t)(b * SEQLEN + l0 + t);
            cpa16ca(smem_u32(&sB[buf][t][seg * 4]),
                    &g_xdbl[row * XPROJ + DT_RANK + seg * 4]);
        } else if (PHASE == 1) {
            int t2 = tid - 256;
            int t = t2 >> 2, seg = t2 & 3;
            size_t row = (size_t)(b * SEQLEN + l0 + t);
            cpa16ca(smem_u32(&sC[buf][t][seg * 4]),
                    &g_xdbl[row * XPROJ + DT_RANK + D_STATE + seg * 4]);
        }
        asm volatile("cp.async.commit_group;" ::: "memory");
    };

    const int NJ = CHLEN / TL;   // 4 sub-chunks
    stage(0);

    for (int j = 0; j < NJ; j++) {
        if (j + 1 < NJ) {
            stage(j + 1);
            asm volatile("cp.async.wait_group 1;" ::: "memory");
        } else {
            asm volatile("cp.async.wait_group 0;" ::: "memory");
        }
        __syncthreads();

        const int buf = j & 1;
#pragma unroll 4
        for (int t = 0; t < TL; t++) {
            float dl = sD[buf][t][dc];
            float u  = sU[buf][t][dc];
            float dA = __expf(dl * An);
            s = fmaf(s, dA, (dl * u) * sB[buf][t][n]);
            if (PHASE == 0) {
                sumdl += dl;
            } else {
                float v = s * sC[buf][t][n];
                v += __shfl_xor_sync(0xffffffffu, v, 8);
                v += __shfl_xor_sync(0xffffffffu, v, 4);
                v += __shfl_xor_sync(0xffffffffu, v, 2);
                v += __shfl_xor_sync(0xffffffffu, v, 1);
                if (n == 0) sY[t][dc] = v;
            }
        }

        if (PHASE == 1) {
            __syncthreads();
            int l0 = lbase + j * TL;
            for (int i = tid; i < TL * 32; i += 512) {
                int t = i >> 5, ch = i & 31;
                size_t row = (size_t)(b * SEQLEN + l0 + t);
                float u  = sU[buf][t][ch];
                float yv = sY[t][ch] + u * Dskip;
                float z  = __half2float(g_xzh[row * (2 * D_INNER) + D_INNER + d0 + ch]);
                yv *= z / (1.f + __expf(-z));
                g_yh[row * D_INNER + d0 + ch] = __float2half_rn(yv);
            }
        }
        __syncthreads();
    }

    if (PHASE == 0) {
        size_t sumIdx = ((size_t)(b * PCHUNK + ck) * D_INNER + d) * D_STATE + n;
        g_sloc[sumIdx] = s;
        g_ddec[sumIdx] = __expf(An * sumdl);
    }
}

// ---------------- launcher --------------------------------------------------
extern "C" void kernel_launch(void* const* d_in, const int* in_sizes, int n_in,
                              void* d_out, int out_size)
{
    const float* hidden     = (const float*)d_in[0];
    const float* in_proj_w  = (const float*)d_in[1];
    const float* conv_w     = (const float*)d_in[2];
    const float* conv_b     = (const float*)d_in[3];
    const float* x_proj_w   = (const float*)d_in[4];
    const float* dt_proj_w  = (const float*)d_in[5];
    const float* dt_proj_b  = (const float*)d_in[6];
    const float* A_log      = (const float*)d_in[7];
    const float* D_skip     = (const float*)d_in[8];
    const float* out_proj_w = (const float*)d_in[9];
    float* out = (float*)d_out;

    cudaFuncSetAttribute(gemm_f16<0>,
                         cudaFuncAttributeMaxDynamicSharedMemorySize, GEMM_SMEM);
    cudaFuncSetAttribute(gemm_f16<1>,
                         cudaFuncAttributeMaxDynamicSharedMemorySize, GEMM_SMEM);
    cudaFuncSetAttribute(gemm_w64,
                         cudaFuncAttributeMaxDynamicSharedMemorySize, WSMEM);

    float *xdbl, *part, *delta;
    __half *xzh, *xch, *dth, *yh, *hh, *w1h, *w3h, *w4h, *w6h;
    cudaGetSymbolAddress((void**)&xzh,   g_xzh);
    cudaGetSymbolAddress((void**)&xdbl,  g_xdbl);
    cudaGetSymbolAddress((void**)&part,  g_part);
    cudaGetSymbolAddress((void**)&delta, g_delta);
    cudaGetSymbolAddress((void**)&xch,   g_xch);
    cudaGetSymbolAddress((void**)&dth,   g_dth);
    cudaGetSymbolAddress((void**)&yh,    g_yh);
    cudaGetSymbolAddress((void**)&hh,    g_hh);
    cudaGetSymbolAddress((void**)&w1h,   g_w1h);
    cudaGetSymbolAddress((void**)&w3h,   g_w3h);
    cudaGetSymbolAddress((void**)&w4h,   g_w4h);
    cudaGetSymbolAddress((void**)&w6h,   g_w6h);

    // launches 0-2: conversions (keeps gemm1 at ncu capture index 3)
    cvt_kernel<<<(2 * D_INNER * D_MODEL / 4 + 255) / 256, 256>>>(
        in_proj_w, w1h, 2 * D_INNER * D_MODEL / 4);
    cvt_kernel<<<(BL * D_MODEL / 4 + 255) / 256, 256>>>(
        hidden, hh, BL * D_MODEL / 4);
    {
        int total = (D_MODEL * D_INNER + XPROJ * D_INNER + D_INNER * DT_RANK) / 4;
        cvt3_kernel<<<(total + 255) / 256, 256>>>(out_proj_w, x_proj_w, dt_proj_w);
    }

    // 1) xz = hidden @ in_proj_w^T (2048 x 4096 x 1024) -> fp16, 64x64 warp tile
    gemm_w64<<<dim3(4096 / 256, BL / 128, 1), 256, WSMEM>>>(
        hh, D_MODEL, w1h, D_MODEL, xzh, 2 * D_INNER,
        BL, 2 * D_INNER, D_MODEL);

    // 2) depthwise conv + SiLU -> xc (fp32) + xch (fp16)
    conv_silu_kernel<<<(BL * D_INNER + 255) / 256, 256>>>(conv_w, conv_b);

    // 3) x_dbl = xc @ x_proj_w^T    (2048 x 96 x 2048), split-K=8 + reduce
    gemm_f16<0><<<dim3(1, BL / 128, KSPLIT), 256, GEMM_SMEM>>>(
        xch, D_INNER, w3h, D_INNER, part, XPROJ,
        BL, XPROJ, D_INNER / KSPLIT, nullptr);
    reduce_part_kernel<<<(BL * XPROJ + 255) / 256, 256>>>();

    // 4) delta = softplus(dt_lr @ dt_proj_w^T + dt_b)  (2048 x 2048 x 64)
    gemm_f16<1><<<dim3(D_INNER / 128, BL / 128, 1), 256, GEMM_SMEM>>>(
        dth, DT_RANK, w4h, DT_RANK, delta, D_INNER,
        BL, D_INNER, DT_RANK, dt_proj_b);

    // 5) chunked selective scan: local pass, then final pass (prefix inlined)
    scan_phase<0><<<dim3(D_INNER / 32, BATCH, PCHUNK), 512>>>(A_log, D_skip);
    scan_phase<1><<<dim3(D_INNER / 32, BATCH, PCHUNK), 512>>>(A_log, D_skip);

    // 6) out = y @ out_proj_w^T     (2048 x 1024 x 2048)
    gemm_f16<0><<<dim3(D_MODEL / 128, BL / 128, 1), 256, GEMM_SMEM>>>(
        yh, D_INNER, w6h, D_INNER, out, D_MODEL,
        BL, D_MODEL, D_INNER, nullptr);
}

// round 16
// speedup vs baseline: 1.0587x; 1.0361x over previous
#include <cuda_runtime.h>
#include <cuda_fp16.h>
#include <math.h>
#include <stdint.h>

#define D_MODEL 1024
#define D_INNER 2048
#define D_STATE 16
#define D_CONV  4
#define DT_RANK 64
#define BATCH   2
#define SEQLEN  1024
#define BL      (BATCH * SEQLEN)          // 2048 rows
#define XPROJ   (DT_RANK + 2 * D_STATE)   // 96
#define KSPLIT  8
#define PCHUNK  8                          // parallel scan chunks
#define CHLEN   (SEQLEN / PCHUNK)          // 128 steps per chunk

// ---------------- scratch (static device globals; no allocs allowed) -------
__device__ __align__(16) __half g_xzh [(size_t)BL * 2 * D_INNER];   // 16 MB
__device__ __align__(16) float  g_xc  [(size_t)BL * D_INNER];       // 16 MB
__device__ __align__(16) __half g_xch [(size_t)BL * D_INNER];
__device__ __align__(16) float  g_xdbl[(size_t)BL * XPROJ];
__device__ __align__(16) float  g_part[(size_t)KSPLIT * BL * XPROJ];
__device__ __align__(16) __half g_dth [(size_t)BL * DT_RANK];
__device__ __align__(16) float  g_delta[(size_t)BL * D_INNER];      // 16 MB
__device__ __align__(16) __half g_yh  [(size_t)BL * D_INNER];
__device__ __align__(16) __half g_hh  [(size_t)BL * D_MODEL];
__device__ __align__(16) __half g_w1h [(size_t)2 * D_INNER * D_MODEL];
__device__ __align__(16) __half g_w3h [(size_t)XPROJ * D_INNER];
__device__ __align__(16) __half g_w4h [(size_t)D_INNER * DT_RANK];
__device__ __align__(16) __half g_w6h [(size_t)D_MODEL * D_INNER];
// scan chunk summaries: [b][chunk][d][n]
__device__ __align__(16) float  g_sloc[(size_t)BATCH * PCHUNK * D_INNER * D_STATE];
__device__ __align__(16) float  g_ddec[(size_t)BATCH * PCHUNK * D_INNER * D_STATE];

// ---------------- tiny PTX helpers -----------------------------------------
__device__ __forceinline__ uint32_t smem_u32(const void* p) {
    uint32_t a;
    asm("{ .reg .u64 t; cvta.to.shared.u64 t, %1; cvt.u32.u64 %0, t; }"
        : "=r"(a) : "l"(p));
    return a;
}
__device__ __forceinline__ uint32_t sw128(uint32_t off) {
    return off ^ ((off >> 3) & 0x70);
}
__device__ __forceinline__ void cpa16(uint32_t dst, const void* src, bool valid) {
    int sz = valid ? 16 : 0;
    asm volatile("cp.async.cg.shared.global [%0], [%1], 16, %2;"
                 :: "r"(dst), "l"(src), "r"(sz));
}
__device__ __forceinline__ void cpa16ca(uint32_t dst, const void* src) {
    asm volatile("cp.async.ca.shared.global [%0], [%1], 16;"
                 :: "r"(dst), "l"(src));
}
__device__ __forceinline__ void ldsm4(uint32_t* r, uint32_t addr) {
    asm volatile("ldmatrix.sync.aligned.m8n8.x4.shared.b16 {%0,%1,%2,%3}, [%4];"
                 : "=r"(r[0]), "=r"(r[1]), "=r"(r[2]), "=r"(r[3]) : "r"(addr));
}
__device__ __forceinline__ void mma_f16(float* d, const uint32_t* a,
                                        uint32_t b0, uint32_t b1) {
    asm volatile(
        "mma.sync.aligned.m16n8k16.row.col.f32.f16.f16.f32 "
        "{%0,%1,%2,%3}, {%4,%5,%6,%7}, {%8,%9}, {%0,%1,%2,%3};"
        : "+f"(d[0]), "+f"(d[1]), "+f"(d[2]), "+f"(d[3])
        : "r"(a[0]), "r"(a[1]), "r"(a[2]), "r"(a[3]), "r"(b0), "r"(b1));
}

// ---------------- fused fp32 -> fp16 conversion (all 5 tensors) -------------
__global__ void cvt_all_kernel(const float* __restrict__ w1,
                               const float* __restrict__ w6,
                               const float* __restrict__ hid,
                               const float* __restrict__ w3,
                               const float* __restrict__ w4)
{
    const int N1 = 2 * D_INNER * D_MODEL / 4;
    const int N6 = D_MODEL * D_INNER / 4;
    const int NH = BL * D_MODEL / 4;
    const int N3 = XPROJ * D_INNER / 4;
    const int N4 = D_INNER * DT_RANK / 4;

    int j = blockIdx.x * blockDim.x + threadIdx.x;
    const float* src; __half* dst;
    if (j < N1)                      { src = w1;  dst = g_w1h; }
    else if ((j -= N1) < N6)         { src = w6;  dst = g_w6h; }
    else if ((j -= N6) < NH)         { src = hid; dst = g_hh;  }
    else if ((j -= NH) < N3)         { src = w3;  dst = g_w3h; }
    else if ((j -= N3) < N4)         { src = w4;  dst = g_w4h; }
    else return;

    float4 v = ((const float4*)src)[j];
    __half2 a = __floats2half2_rn(v.x, v.y);
    __half2 b = __floats2half2_rn(v.z, v.w);
    ((uint2*)dst)[j] = make_uint2(*(uint32_t*)&a, *(uint32_t*)&b);
}

// ---------------- HMMA fp16 GEMM, 256 thr, 128x128 tile --------------------
// C[M,N] = A[M,K] * B[N,K]^T, fp16 in, fp32 accum.
// 8 warps 4(M)x2(N); warp tile 32x64; KC=64; 3-stage cp.async; one barrier
// per chunk.  EPI: 0=fp32 store, 1=bias+softplus fp32, 2=fp16 store.
#define KC 64
#define TILE_B   (128 * 128)
#define STAGE_B  (2 * TILE_B)
#define NSTAGE   3
#define GEMM_SMEM (NSTAGE * STAGE_B + 1024)

template <int EPI>
__global__ __launch_bounds__(256, 2)
void gemm_f16(const __half* __restrict__ A, int lda,
              const __half* __restrict__ B, int ldb,
              void* __restrict__ Cv, int ldc,
              int M, int N, int Kslice,
              const float* __restrict__ bias)
{
    extern __shared__ __align__(16) char dyns[];

    const int tid  = threadIdx.x;
    const int wid  = tid >> 5;
    const int lane = tid & 31;
    const int row0 = blockIdx.y * 128;
    const int col0 = blockIdx.x * 128;
    const int kBeg = blockIdx.z * Kslice;
    const int nB = min(128, N - col0);
    const int chunks = Kslice / KC;

    float*  Cf = (float*)Cv  + (size_t)blockIdx.z * (size_t)M * (size_t)ldc;
    __half* Ch = (__half*)Cv;

    const int warp_m = wid & 3;
    const int warp_n = wid >> 2;

    uint32_t sbase = (smem_u32(dyns) + 1023u) & ~1023u;

    float acc[2][8][4];
#pragma unroll
    for (int i = 0; i < 2; i++)
#pragma unroll
        for (int j = 0; j < 8; j++)
#pragma unroll
            for (int k = 0; k < 4; k++) acc[i][j][k] = 0.f;

    auto load_chunk = [&](int c) {
        uint32_t st = sbase + (uint32_t)(c % NSTAGE) * STAGE_B;
        int kcol = kBeg + c * KC;
        int seg = tid & 7;
#pragma unroll
        for (int j = 0; j < 4; j++) {
            int row = (tid >> 3) + j * 32;
            uint32_t so = sw128((uint32_t)(row * 128 + seg * 16));
            const __half* pa = A + (size_t)(row0 + row) * lda + kcol + seg * 8;
            cpa16(st + so, pa, true);
            bool bv = row < nB;
            int  br = bv ? row : 0;
            const __half* pb = B + (size_t)(col0 + br) * ldb + kcol + seg * 8;
            cpa16(st + TILE_B + so, pb, bv);
        }
        asm volatile("cp.async.commit_group;" ::: "memory");
    };

#pragma unroll
    for (int p = 0; p < NSTAGE - 1; p++)
        if (p < chunks) load_chunk(p);

    const int lrow  = lane & 15;
    const int lhalf = lane >> 4;

    uint32_t swa[2], swb[4];
#pragma unroll
    for (int mf = 0; mf < 2; mf++)
        swa[mf] = sw128((uint32_t)((warp_m * 32 + mf * 16 + lrow) * 128));
#pragma unroll
    for (int nf = 0; nf < 4; nf++)
        swb[nf] = sw128((uint32_t)((warp_n * 64 + nf * 16 + lrow) * 128)) + TILE_B;

    for (int c = 0; c < chunks; c++) {
        int pend = chunks - 1 - c;
        if (pend > NSTAGE - 2) pend = NSTAGE - 2;
        if (pend == 1) asm volatile("cp.async.wait_group 1;" ::: "memory");
        else           asm volatile("cp.async.wait_group 0;" ::: "memory");
        __syncthreads();      // single barrier per chunk

        if (c + NSTAGE - 1 < chunks) load_chunk(c + NSTAGE - 1);

        uint32_t st = sbase + (uint32_t)(c % NSTAGE) * STAGE_B;

#pragma unroll
        for (int ks = 0; ks < KC / 16; ks++) {
            const uint32_t kb = (uint32_t)(ks * 32 + lhalf * 16);
            uint32_t af[2][4], bf[4][4];
            ldsm4(af[0], (st + swa[0]) ^ kb);
            ldsm4(af[1], (st + swa[1]) ^ kb);
            ldsm4(bf[0], (st + swb[0]) ^ kb);
            ldsm4(bf[1], (st + swb[1]) ^ kb);
            ldsm4(bf[2], (st + swb[2]) ^ kb);
            ldsm4(bf[3], (st + swb[3]) ^ kb);
#pragma unroll
            for (int mf = 0; mf < 2; mf++) {
#pragma unroll
                for (int nf = 0; nf < 4; nf++) {
                    mma_f16(acc[mf][2 * nf],     af[mf], bf[nf][0], bf[nf][2]);
                    mma_f16(acc[mf][2 * nf + 1], af[mf], bf[nf][1], bf[nf][3]);
                }
            }
        }
    }
    __syncthreads();

#pragma unroll
    for (int mf = 0; mf < 2; mf++) {
        int r = row0 + warp_m * 32 + mf * 16 + (lane >> 2);
#pragma unroll
        for (int j = 0; j < 8; j++) {
            int ccol = col0 + warp_n * 64 + j * 8 + (lane & 3) * 2;
            if (ccol < N) {
                float v0 = acc[mf][j][0], v1 = acc[mf][j][1];
                float v2 = acc[mf][j][2], v3 = acc[mf][j][3];
                if (EPI == 1) {
                    v0 += bias[ccol];     v1 += bias[ccol + 1];
                    v2 += bias[ccol];     v3 += bias[ccol + 1];
                    v0 = (v0 > 20.f) ? v0 : log1pf(__expf(v0));
                    v1 = (v1 > 20.f) ? v1 : log1pf(__expf(v1));
                    v2 = (v2 > 20.f) ? v2 : log1pf(__expf(v2));
                    v3 = (v3 > 20.f) ? v3 : log1pf(__expf(v3));
                }
                if (EPI == 2) {
                    __half2 h0 = __floats2half2_rn(v0, v1);
                    __half2 h1 = __floats2half2_rn(v2, v3);
                    *(__half2*)&Ch[(size_t)r * ldc + ccol]       = h0;
                    *(__half2*)&Ch[(size_t)(r + 8) * ldc + ccol] = h1;
                } else {
                    *(float2*)&Cf[(size_t)r * ldc + ccol]       = make_float2(v0, v1);
                    *(float2*)&Cf[(size_t)(r + 8) * ldc + ccol] = make_float2(v2, v3);
                }
            }
        }
    }
}

// ---------------- reduce split-K partials + dt_lr fp16 ----------------------
__global__ void reduce_part_kernel()
{
    int i = blockIdx.x * blockDim.x + threadIdx.x;
    if (i < BL * XPROJ) {
        float s = 0.f;
#pragma unroll
        for (int p = 0; p < KSPLIT; p++)
            s += g_part[(size_t)p * BL * XPROJ + i];
        g_xdbl[i] = s;
        int col = i % XPROJ;
        if (col < DT_RANK) {
            int row = i / XPROJ;
            g_dth[(size_t)row * DT_RANK + col] = __float2half_rn(s);
        }
    }
}

// ---------------- depthwise causal conv + bias + SiLU -----------------------
__global__ void conv_silu_kernel(const float* __restrict__ w,
                                 const float* __restrict__ bias)
{
    int idx = blockIdx.x * blockDim.x + threadIdx.x;
    if (idx >= BL * D_INNER) return;
    int d  = idx % D_INNER;
    int bl = idx / D_INNER;
    int l  = bl % SEQLEN;

    float acc = bias[d];
#pragma unroll
    for (int k = 0; k < D_CONV; k++) {
        int lk = l - (D_CONV - 1) + k;
        if (lk >= 0)
            acc += w[d * D_CONV + k] *
                   __half2float(g_xzh[(size_t)(bl - (D_CONV - 1 - k)) * (2 * D_INNER) + d]);
    }
    float sg = 1.f / (1.f + __expf(-acc));
    float v = acc * sg;
    g_xc[idx]  = v;
    g_xch[idx] = __float2half_rn(v);
}

// ---------------- chunked selective scan ------------------------------------
// PHASE 0: per chunk local scan from 0; emit s_loc + decay.
// PHASE 1: inline prefix over chunk summaries -> true start state; scan,
//          emit gated y (fp16).
#define TL 64
template <int PHASE>
__global__ __launch_bounds__(512)
void scan_phase(const float* __restrict__ A_log,
                const float* __restrict__ D_skip)
{
    __shared__ float sD[2][TL][32];
    __shared__ float sU[2][TL][32];
    __shared__ float sB[2][TL][16];
    __shared__ float sC[2][TL][16];
    __shared__ float sY[TL][32];

    const int b    = blockIdx.y;
    const int ck   = blockIdx.z;
    const int d0   = blockIdx.x * 32;
    const int tid  = threadIdx.x;
    const int dc   = tid >> 4;
    const int n    = tid & 15;
    const int d    = d0 + dc;
    const int lbase = ck * CHLEN;

    const float An = -__expf(A_log[d * D_STATE + n]);

    float s = 0.f;
    if (PHASE == 1) {
        // inline prefix over earlier chunks (<= PCHUNK-1 iterations)
        for (int c = 0; c < ck; c++) {
            size_t idx = ((size_t)(b * PCHUNK + c) * D_INNER + d) * D_STATE + n;
            s = s * g_ddec[idx] + g_sloc[idx];
        }
    }
    float sumdl = 0.f;
    const float Dskip = D_skip[d0 + (tid & 31)];

    auto stage = [&](int j) {
        int buf = j & 1;
        int l0 = lbase + j * TL;
        {
            int t = tid >> 3, seg = tid & 7;
            size_t row = (size_t)(b * SEQLEN + l0 + t);
            cpa16ca(smem_u32(&sD[buf][t][seg * 4]),
                    &g_delta[row * D_INNER + d0 + seg * 4]);
            cpa16ca(smem_u32(&sU[buf][t][seg * 4]),
                    &g_xc[row * D_INNER + d0 + seg * 4]);
        }
        if (tid < 256) {
            int t = tid >> 2, seg = tid & 3;
            size_t row = (size_t)(b * SEQLEN + l0 + t);
            cpa16ca(smem_u32(&sB[buf][t][seg * 4]),
                    &g_xdbl[row * XPROJ + DT_RANK + seg * 4]);
        } else if (PHASE == 1) {
            int t2 = tid - 256;
            int t = t2 >> 2, seg = t2 & 3;
            size_t row = (size_t)(b * SEQLEN + l0 + t);
            cpa16ca(smem_u32(&sC[buf][t][seg * 4]),
                    &g_xdbl[row * XPROJ + DT_RANK + D_STATE + seg * 4]);
        }
        asm volatile("cp.async.commit_group;" ::: "memory");
    };

    const int NJ = CHLEN / TL;   // 2 sub-chunks
    stage(0);

    for (int j = 0; j < NJ; j++) {
        if (j + 1 < NJ) {
            stage(j + 1);
            asm volatile("cp.async.wait_group 1;" ::: "memory");
        } else {
            asm volatile("cp.async.wait_group 0;" ::: "memory");
        }
        __syncthreads();

        const int buf = j & 1;
#pragma unroll 4
        for (int t = 0; t < TL; t++) {
            float dl = sD[buf][t][dc];
            float u  = sU[buf][t][dc];
            float dA = __expf(dl * An);
            s = fmaf(s, dA, (dl * u) * sB[buf][t][n]);
            if (PHASE == 0) {
                sumdl += dl;
            } else {
                float v = s * sC[buf][t][n];
                v += __shfl_xor_sync(0xffffffffu, v, 8);
                v += __shfl_xor_sync(0xffffffffu, v, 4);
                v += __shfl_xor_sync(0xffffffffu, v, 2);
                v += __shfl_xor_sync(0xffffffffu, v, 1);
                if (n == 0) sY[t][dc] = v;
            }
        }

        if (PHASE == 1) {
            __syncthreads();
            int l0 = lbase + j * TL;
            for (int i = tid; i < TL * 32; i += 512) {
                int t = i >> 5, ch = i & 31;
                size_t row = (size_t)(b * SEQLEN + l0 + t);
                float u  = sU[buf][t][ch];
                float yv = sY[t][ch] + u * Dskip;
                float z  = __half2float(g_xzh[row * (2 * D_INNER) + D_INNER + d0 + ch]);
                yv *= z / (1.f + __expf(-z));
                g_yh[row * D_INNER + d0 + ch] = __float2half_rn(yv);
            }
        }
        __syncthreads();
    }

    if (PHASE == 0) {
        size_t sumIdx = ((size_t)(b * PCHUNK + ck) * D_INNER + d) * D_STATE + n;
        g_sloc[sumIdx] = s;
        g_ddec[sumIdx] = __expf(An * sumdl);
    }
}

// ---------------- launcher --------------------------------------------------
extern "C" void kernel_launch(void* const* d_in, const int* in_sizes, int n_in,
                              void* d_out, int out_size)
{
    const float* hidden     = (const float*)d_in[0];
    const float* in_proj_w  = (const float*)d_in[1];
    const float* conv_w     = (const float*)d_in[2];
    const float* conv_b     = (const float*)d_in[3];
    const float* x_proj_w   = (const float*)d_in[4];
    const float* dt_proj_w  = (const float*)d_in[5];
    const float* dt_proj_b  = (const float*)d_in[6];
    const float* A_log      = (const float*)d_in[7];
    const float* D_skip     = (const float*)d_in[8];
    const float* out_proj_w = (const float*)d_in[9];
    float* out = (float*)d_out;

    cudaFuncSetAttribute(gemm_f16<0>,
                         cudaFuncAttributeMaxDynamicSharedMemorySize, GEMM_SMEM);
    cudaFuncSetAttribute(gemm_f16<1>,
                         cudaFuncAttributeMaxDynamicSharedMemorySize, GEMM_SMEM);
    cudaFuncSetAttribute(gemm_f16<2>,
                         cudaFuncAttributeMaxDynamicSharedMemorySize, GEMM_SMEM);

    float *xdbl, *part, *delta;
    __half *xzh, *xch, *dth, *yh, *hh, *w1h, *w3h, *w4h, *w6h;
    cudaGetSymbolAddress((void**)&xzh,   g_xzh);
    cudaGetSymbolAddress((void**)&xdbl,  g_xdbl);
    cudaGetSymbolAddress((void**)&part,  g_part);
    cudaGetSymbolAddress((void**)&delta, g_delta);
    cudaGetSymbolAddress((void**)&xch,   g_xch);
    cudaGetSymbolAddress((void**)&dth,   g_dth);
    cudaGetSymbolAddress((void**)&yh,    g_yh);
    cudaGetSymbolAddress((void**)&hh,    g_hh);
    cudaGetSymbolAddress((void**)&w1h,   g_w1h);
    cudaGetSymbolAddress((void**)&w3h,   g_w3h);
    cudaGetSymbolAddress((void**)&w4h,   g_w4h);
    cudaGetSymbolAddress((void**)&w6h,   g_w6h);

    // 0) all fp32->fp16 conversions in one launch
    {
        int total = (2 * D_INNER * D_MODEL + D_MODEL * D_INNER + BL * D_MODEL +
                     XPROJ * D_INNER + D_INNER * DT_RANK) / 4;
        cvt_all_kernel<<<(total + 255) / 256, 256>>>(in_proj_w, out_proj_w,
                                                     hidden, x_proj_w, dt_proj_w);
    }

    // 1) xz = hidden @ in_proj_w^T   (2048 x 4096 x 1024) -> fp16
    gemm_f16<2><<<dim3(4096 / 128, BL / 128, 1), 256, GEMM_SMEM>>>(
        hh, D_MODEL, w1h, D_MODEL, xzh, 2 * D_INNER,
        BL, 2 * D_INNER, D_MODEL, nullptr);

    // 2) depthwise conv + SiLU -> xc (fp32) + xch (fp16)
    conv_silu_kernel<<<(BL * D_INNER + 255) / 256, 256>>>(conv_w, conv_b);

    // 3) x_dbl = xc @ x_proj_w^T    (2048 x 96 x 2048), split-K=8 + reduce
    gemm_f16<0><<<dim3(1, BL / 128, KSPLIT), 256, GEMM_SMEM>>>(
        xch, D_INNER, w3h, D_INNER, part, XPROJ,
        BL, XPROJ, D_INNER / KSPLIT, nullptr);
    reduce_part_kernel<<<(BL * XPROJ + 255) / 256, 256>>>();

    // 4) delta = softplus(dt_lr @ dt_proj_w^T + dt_b)  (2048 x 2048 x 64)
    gemm_f16<1><<<dim3(D_INNER / 128, BL / 128, 1), 256, GEMM_SMEM>>>(
        dth, DT_RANK, w4h, DT_RANK, delta, D_INNER,
        BL, D_INNER, DT_RANK, dt_proj_b);

    // 5) chunked selective scan: local pass, then final pass (prefix inlined)
    scan_phase<0><<<dim3(D_INNER / 32, BATCH, PCHUNK), 512>>>(A_log, D_skip);
    scan_phase<1><<<dim3(D_INNER / 32, BATCH, PCHUNK), 512>>>(A_log, D_skip);

    // 6) out = y @ out_proj_w^T     (2048 x 1024 x 2048)
    gemm_f16<0><<<dim3(D_MODEL / 128, BL / 128, 1), 256, GEMM_SMEM>>>(
        yh, D_INNER, w6h, D_INNER, out, D_MODEL,
        BL, D_MODEL, D_INNER, nullptr);
}